// round 1
// baseline (speedup 1.0000x reference)
#include <cuda_runtime.h>
#include <math.h>

#define BSZ   128
#define NIMG  256
#define CH    64
#define NPX   4096      // 64*64
#define HID   128

// ---------------- scratch (device globals; no allocation) ----------------
__device__ float g_feat1[NIMG * CH * NPX];   // conv1 out, later final features
__device__ float g_feat2[NIMG * CH * NPX];   // conv2 out
__device__ float g_bnab[2][2][64][2];        // [stage][group][c][{scale,shift}]
__device__ float g_Hx[BSZ * HID];
__device__ float g_Cx[BSZ * HID];
__device__ float g_Fh[BSZ * 8 * 64];
__device__ float g_Fw[BSZ * 8 * 64];
__device__ float g_flat[BSZ * 4096];
__device__ float g_gatesP[16 * BSZ * 512];   // split-K partials

// ---------------- init ----------------
__global__ void k_zero() {
    int i = blockIdx.x * blockDim.x + threadIdx.x;
    if (i < BSZ * HID) { g_Hx[i] = 0.f; g_Cx[i] = 0.f; }
}

// ---------------- conv1: 1 -> 64, 3x3 SAME, + bias ----------------
__global__ __launch_bounds__(256) void k_conv1(const float* __restrict__ img,
                                               const float* __restrict__ w1,
                                               const float* __restrict__ b1) {
    int n = blockIdx.x;            // 0..255
    __shared__ float s[66 * 66];
    __shared__ float ws[64 * 9];
    __shared__ float bs[64];
    int tid = threadIdx.x;

    for (int e = tid; e < 66 * 66; e += 256) s[e] = 0.f;
    for (int e = tid; e < 576; e += 256) ws[e] = w1[e];
    if (tid < 64) bs[tid] = b1[tid];
    __syncthreads();
    const float* ip = img + (size_t)n * NPX;
    for (int e = tid; e < NPX; e += 256) {
        int y = e >> 6, x = e & 63;
        s[(y + 1) * 66 + (x + 1)] = ip[e];
    }
    __syncthreads();

    float* op = g_feat1 + (size_t)n * CH * NPX;
    for (int c0 = 0; c0 < 64; c0 += 4) {
        float wr[36], bb[4];
        #pragma unroll
        for (int cc = 0; cc < 4; cc++) {
            bb[cc] = bs[c0 + cc];
            #pragma unroll
            for (int q = 0; q < 9; q++) wr[cc * 9 + q] = ws[(c0 + cc) * 9 + q];
        }
        for (int k = 0; k < 16; k++) {
            int p = tid + 256 * k;
            int y = p >> 6, x = p & 63;
            float nb[9];
            #pragma unroll
            for (int dy = 0; dy < 3; dy++)
                #pragma unroll
                for (int dx = 0; dx < 3; dx++)
                    nb[dy * 3 + dx] = s[(y + dy) * 66 + x + dx];
            #pragma unroll
            for (int cc = 0; cc < 4; cc++) {
                float a = bb[cc];
                #pragma unroll
                for (int q = 0; q < 9; q++) a = fmaf(wr[cc * 9 + q], nb[q], a);
                op[(size_t)(c0 + cc) * NPX + p] = a;
            }
        }
    }
}

// ---------------- BN stats (deterministic, no atomics) ----------------
// block = (group g, channel c): reduce over 128 images * 4096 px
__global__ __launch_bounds__(256) void k_bnstats(const float* __restrict__ gamma,
                                                 const float* __restrict__ beta,
                                                 int stage) {
    const float* src = stage ? g_feat2 : g_feat1;
    int g = blockIdx.x >> 6, c = blockIdx.x & 63;
    int tid = threadIdx.x;
    float s = 0.f, q = 0.f;
    for (int b = 0; b < 128; b++) {
        const float* p = src + ((size_t)(2 * b + g) * CH + c) * NPX;
        for (int e = tid; e < NPX; e += 256) { float v = p[e]; s += v; q += v * v; }
    }
    __shared__ float rs[256], rq[256];
    rs[tid] = s; rq[tid] = q; __syncthreads();
    for (int st = 128; st > 0; st >>= 1) {
        if (tid < st) { rs[tid] += rs[tid + st]; rq[tid] += rq[tid + st]; }
        __syncthreads();
    }
    if (tid == 0) {
        float mean = rs[0] * (1.f / 524288.f);
        float var  = rq[0] * (1.f / 524288.f) - mean * mean;
        float a = gamma[c] * rsqrtf(var + 1e-5f);
        g_bnab[stage][g][c][0] = a;
        g_bnab[stage][g][c][1] = beta[c] - mean * a;
    }
}

// ---------------- conv2: 64 -> 64, input = relu(bn1(feat1)) on the fly ----------------
// block: one image n, 4-row x 64-col pixel tile, all 64 co.
// 256 thr = 8 co-thr x 32 px-thr ; per-thread 8co x 8px register tile.
__global__ __launch_bounds__(256, 2) void k_conv2(const float* __restrict__ w2,
                                                  const float* __restrict__ b2) {
    __shared__ __align__(16) float in_s[8][6][72];
    __shared__ float w_s[64][76];
    __shared__ float ab_s[64][2];

    int n  = blockIdx.x >> 4;
    int y0 = (blockIdx.x & 15) * 4;
    int g  = n & 1;
    int tid = threadIdx.x;
    int pxthr = tid & 31, cothr = tid >> 5;
    int r = pxthr >> 3, tcol = (pxthr & 7) * 8;
    int co0 = cothr * 8;

    if (tid < 128) ab_s[tid >> 1][tid & 1] = g_bnab[0][g][tid >> 1][tid & 1];
    __syncthreads();

    float acc[8][8];
    #pragma unroll
    for (int j = 0; j < 8; j++)
        #pragma unroll
        for (int p = 0; p < 8; p++) acc[j][p] = 0.f;

    const float* f1 = g_feat1 + (size_t)n * CH * NPX;

    for (int ci0 = 0; ci0 < 64; ci0 += 8) {
        // fill input tile (BN+ReLU applied, zero pad)
        for (int e = tid; e < 8 * 6 * 72; e += 256) {
            int ciL = e / 432; int rem = e - ciL * 432;
            int row = rem / 72; int col = rem - row * 72;
            int y = y0 - 1 + row; int x = col - 1;
            float v = 0.f;
            if (y >= 0 && y < 64 && x >= 0 && x < 64) {
                float t = f1[(size_t)(ci0 + ciL) * NPX + y * 64 + x];
                v = fmaxf(fmaf(ab_s[ci0 + ciL][0], t, ab_s[ci0 + ciL][1]), 0.f);
            }
            in_s[ciL][row][col] = v;
        }
        // fill weight tile: w_s[co][kk], kk = ciL*9 + dy*3 + dx
        for (int e = tid; e < 64 * 72; e += 256) {
            int co = e / 72; int kk = e - co * 72;
            w_s[co][kk] = w2[(size_t)co * 576 + ci0 * 9 + kk];
        }
        __syncthreads();

        for (int ciL = 0; ciL < 8; ciL++) {
            #pragma unroll
            for (int dy = 0; dy < 3; dy++) {
                const float4* bp = (const float4*)&in_s[ciL][r + dy][tcol];
                float4 v0 = bp[0], v1 = bp[1], v2 = bp[2];
                float bseg[12] = {v0.x, v0.y, v0.z, v0.w, v1.x, v1.y, v1.z, v1.w,
                                  v2.x, v2.y, v2.z, v2.w};
                #pragma unroll
                for (int dx = 0; dx < 3; dx++) {
                    int kk = ciL * 9 + dy * 3 + dx;
                    float a[8];
                    #pragma unroll
                    for (int j = 0; j < 8; j++) a[j] = w_s[co0 + j][kk];
                    #pragma unroll
                    for (int j = 0; j < 8; j++)
                        #pragma unroll
                        for (int p = 0; p < 8; p++)
                            acc[j][p] = fmaf(a[j], bseg[p + dx], acc[j][p]);
                }
            }
        }
        __syncthreads();
    }

    float* f2 = g_feat2 + (size_t)n * CH * NPX + (size_t)(y0 + r) * 64 + tcol;
    #pragma unroll
    for (int j = 0; j < 8; j++) {
        float bias = b2[co0 + j];
        float4 o0 = make_float4(acc[j][0] + bias, acc[j][1] + bias,
                                acc[j][2] + bias, acc[j][3] + bias);
        float4 o1 = make_float4(acc[j][4] + bias, acc[j][5] + bias,
                                acc[j][6] + bias, acc[j][7] + bias);
        *(float4*)(f2 + (size_t)(co0 + j) * NPX)     = o0;
        *(float4*)(f2 + (size_t)(co0 + j) * NPX + 4) = o1;
    }
}

// ---------------- bn2 + residual(+orig image broadcast) + relu ----------------
__global__ __launch_bounds__(256) void k_residual(const float* __restrict__ img) {
    size_t e = ((size_t)blockIdx.x * 256 + threadIdx.x) * 4;
    int n = (int)(e >> 18);            // / 262144
    int c = (int)((e >> 12) & 63);
    int p = (int)(e & 4095);
    int g = n & 1;
    float a = g_bnab[1][g][c][0], b = g_bnab[1][g][c][1];
    float4 v = *(const float4*)(g_feat2 + e);
    float4 x = *(const float4*)(img + (size_t)n * NPX + p);
    float4 o;
    o.x = fmaxf(fmaf(a, v.x, b) + x.x, 0.f);
    o.y = fmaxf(fmaf(a, v.y, b) + x.y, 0.f);
    o.z = fmaxf(fmaf(a, v.z, b) + x.z, 0.f);
    o.w = fmaxf(fmaf(a, v.w, b) + x.w, 0.f);
    *(float4*)(g_feat1 + e) = o;
}

// ---------------- glimpser linear + Cauchy filterbanks ----------------
__global__ __launch_bounds__(64) void k_filters(const float* __restrict__ gw,
                                                const float* __restrict__ gb) {
    int b = blockIdx.x, tid = threadIdx.x;            // 64 threads
    __shared__ float red[64];
    __shared__ float gp_s[3];
    __shared__ float ps[2][8];
    const float* hx = g_Hx + b * HID;

    for (int rix = 0; rix < 3; rix++) {
        float s = hx[tid] * gw[rix * 128 + tid] + hx[tid + 64] * gw[rix * 128 + tid + 64];
        red[tid] = s; __syncthreads();
        for (int st = 32; st > 0; st >>= 1) {
            if (tid < st) red[tid] += red[tid + st];
            __syncthreads();
        }
        if (tid == 0) gp_s[rix] = tanhf(red[0] + gb[rix]);
        __syncthreads();
    }

    float d = gp_s[2];
    float delta = 8.f * (1.f - fabsf(d));
    float gamma = expf(1.f - 2.f * fabsf(d));
    float inv_g = 1.f / gamma;
    float fi = (float)tid;
    int lane = tid & 31, wrp = tid >> 5;

    for (int fs = 0; fs < 2; fs++) {
        float center = 31.5f * (gp_s[fs] + 1.f);
        float f[8];
        #pragma unroll
        for (int gg = 0; gg < 8; gg++) {
            float gpos = center + delta * ((float)gg - 3.5f);
            float u = (fi - gpos) * inv_g;
            f[gg] = 1.f / (3.14159265358979323846f * gamma * (1.f + u * u));
        }
        #pragma unroll
        for (int gg = 0; gg < 8; gg++) {
            float s = f[gg];
            for (int off = 16; off > 0; off >>= 1) s += __shfl_down_sync(0xffffffffu, s, off);
            if (lane == 0) ps[wrp][gg] = s;
        }
        __syncthreads();
        float* out = (fs ? g_Fw : g_Fh) + b * 512;
        #pragma unroll
        for (int gg = 0; gg < 8; gg++) {
            float sum = ps[0][gg] + ps[1][gg];
            out[gg * 64 + tid] = f[gg] / (sum + 1e-4f);
        }
        __syncthreads();
    }
}

// ---------------- glimpse: gl = Fh * img * Fw^T, per channel ----------------
// grid 256 = (b, half-of-channels). thread: (c_local 0..15, j0 = 4*(tid&15))
__global__ __launch_bounds__(256) void k_glimpse(int par) {
    int b = blockIdx.x >> 1, half = blockIdx.x & 1;
    int n = 2 * b + par;
    int tid = threadIdx.x;
    int cl = tid >> 4, j0 = (tid & 15) * 4;

    __shared__ float Fh_s[512], Fw_s[512];
    __shared__ __align__(16) float t_s[16][8][64];

    for (int e = tid; e < 512; e += 256) { Fh_s[e] = g_Fh[b * 512 + e]; Fw_s[e] = g_Fw[b * 512 + e]; }
    __syncthreads();

    for (int cb = 0; cb < 2; cb++) {
        int c = half * 32 + cb * 16 + cl;
        const float* ip = g_feat1 + ((size_t)n * CH + c) * NPX;
        float acc[8][4];
        #pragma unroll
        for (int gg = 0; gg < 8; gg++)
            #pragma unroll
            for (int q = 0; q < 4; q++) acc[gg][q] = 0.f;

        #pragma unroll 4
        for (int i = 0; i < 64; i++) {
            float4 v = *(const float4*)(ip + i * 64 + j0);
            #pragma unroll
            for (int gg = 0; gg < 8; gg++) {
                float fh = Fh_s[gg * 64 + i];
                acc[gg][0] = fmaf(fh, v.x, acc[gg][0]);
                acc[gg][1] = fmaf(fh, v.y, acc[gg][1]);
                acc[gg][2] = fmaf(fh, v.z, acc[gg][2]);
                acc[gg][3] = fmaf(fh, v.w, acc[gg][3]);
            }
        }
        #pragma unroll
        for (int gg = 0; gg < 8; gg++)
            *(float4*)&t_s[cl][gg][j0] = make_float4(acc[gg][0], acc[gg][1], acc[gg][2], acc[gg][3]);
        __syncthreads();

        // gl[c][g][w] = sum_j t[c][g][j] * Fw[w][j] ; 1024 outputs, 4/thread
        #pragma unroll
        for (int k = 0; k < 4; k++) {
            int o = tid + 256 * k;
            int cc = o >> 6, gg = (o >> 3) & 7, w = o & 7;
            float s = 0.f;
            #pragma unroll 8
            for (int jj = 0; jj < 64; jj++) s = fmaf(t_s[cc][gg][jj], Fw_s[w * 64 + jj], s);
            int cglob = half * 32 + cb * 16 + cc;
            g_flat[b * 4096 + cglob * 64 + gg * 8 + w] = s;
        }
        __syncthreads();
    }
}

// ---------------- LSTM gates GEMM: gatesP[ks] = flat_chunk @ Wih_chunk^T ----------------
// grid (8 N-tiles, 16 K-splits); block tile M=128, N=64, K=256
__global__ __launch_bounds__(256) void k_gates(const float* __restrict__ wih) {
    __shared__ __align__(16) float A_s[16][132];
    __shared__ __align__(16) float B_s[16][68];
    int tid = threadIdx.x;
    int mt = tid & 15, nt = tid >> 4;
    int r0 = blockIdx.x * 64;
    int kbase = blockIdx.y * 256;

    float acc[8][4];
    #pragma unroll
    for (int i = 0; i < 8; i++)
        #pragma unroll
        for (int j = 0; j < 4; j++) acc[i][j] = 0.f;

    for (int k0 = 0; k0 < 256; k0 += 16) {
        for (int e = tid; e < 2048; e += 256) {
            int bb = e >> 4, kk = e & 15;
            A_s[kk][bb] = g_flat[bb * 4096 + kbase + k0 + kk];
        }
        for (int e = tid; e < 1024; e += 256) {
            int rr = e >> 4, kk = e & 15;
            B_s[kk][rr] = wih[(size_t)(r0 + rr) * 4096 + kbase + k0 + kk];
        }
        __syncthreads();
        #pragma unroll
        for (int kk = 0; kk < 16; kk++) {
            float4 a0 = *(const float4*)&A_s[kk][mt * 8];
            float4 a1 = *(const float4*)&A_s[kk][mt * 8 + 4];
            float4 bv = *(const float4*)&B_s[kk][nt * 4];
            float a[8] = {a0.x, a0.y, a0.z, a0.w, a1.x, a1.y, a1.z, a1.w};
            float bb[4] = {bv.x, bv.y, bv.z, bv.w};
            #pragma unroll
            for (int i = 0; i < 8; i++)
                #pragma unroll
                for (int j = 0; j < 4; j++)
                    acc[i][j] = fmaf(a[i], bb[j], acc[i][j]);
        }
        __syncthreads();
    }
    #pragma unroll
    for (int i = 0; i < 8; i++)
        #pragma unroll
        for (int j = 0; j < 4; j++)
            g_gatesP[((size_t)blockIdx.y * 128 + mt * 8 + i) * 512 + r0 + nt * 4 + j] = acc[i][j];
}

// ---------------- LSTM reduce + Hx@Whh^T + pointwise update ----------------
__global__ __launch_bounds__(128) void k_update(const float* __restrict__ whh,
                                                const float* __restrict__ bih,
                                                const float* __restrict__ bhh) {
    int b = blockIdx.x, j = threadIdx.x;
    __shared__ float hx_s[128];
    hx_s[j] = g_Hx[b * 128 + j];
    __syncthreads();
    float gate[4];
    #pragma unroll
    for (int q = 0; q < 4; q++) {
        int rr = q * 128 + j;
        float s = bih[rr] + bhh[rr];
        #pragma unroll
        for (int ks = 0; ks < 16; ks++) s += g_gatesP[((size_t)ks * 128 + b) * 512 + rr];
        const float* w = whh + (size_t)rr * 128;
        float s2 = 0.f;
        #pragma unroll 8
        for (int h = 0; h < 128; h++) s2 = fmaf(hx_s[h], w[h], s2);
        gate[q] = s + s2;
    }
    float ig = 1.f / (1.f + expf(-gate[0]));
    float fg = 1.f / (1.f + expf(-gate[1]));
    float gg = tanhf(gate[2]);
    float og = 1.f / (1.f + expf(-gate[3]));
    float cx = fg * g_Cx[b * 128 + j] + ig * gg;
    g_Cx[b * 128 + j] = cx;
    g_Hx[b * 128 + j] = og * tanhf(cx);
}

__global__ void k_copyout(float* __restrict__ out) {
    int i = blockIdx.x * blockDim.x + threadIdx.x;
    if (i < BSZ * HID) out[i] = g_Hx[i];
}

// ---------------- launch ----------------
extern "C" void kernel_launch(void* const* d_in, const int* in_sizes, int n_in,
                              void* d_out, int out_size) {
    const float* img  = (const float*)d_in[0];
    const float* c1w  = (const float*)d_in[1];
    const float* c1b  = (const float*)d_in[2];
    const float* bn1g = (const float*)d_in[3];
    const float* bn1b = (const float*)d_in[4];
    const float* c2w  = (const float*)d_in[5];
    const float* c2b  = (const float*)d_in[6];
    const float* bn2g = (const float*)d_in[7];
    const float* bn2b = (const float*)d_in[8];
    const float* wih  = (const float*)d_in[9];
    const float* whh  = (const float*)d_in[10];
    const float* bih  = (const float*)d_in[11];
    const float* bhh  = (const float*)d_in[12];
    const float* gw   = (const float*)d_in[13];
    const float* gb   = (const float*)d_in[14];
    float* out = (float*)d_out;

    k_zero<<<32, 512>>>();
    k_conv1<<<256, 256>>>(img, c1w, c1b);
    k_bnstats<<<128, 256>>>(bn1g, bn1b, 0);
    k_conv2<<<4096, 256>>>(c2w, c2b);
    k_bnstats<<<128, 256>>>(bn2g, bn2b, 1);
    k_residual<<<65536, 256>>>(img);

    for (int turn = 0; turn < 16; ++turn) {
        int par = (turn & 1) ? 0 : 1;   // even turn -> test (pair 1), odd -> support (pair 0)
        k_filters<<<128, 64>>>(gw, gb);
        k_glimpse<<<256, 256>>>(par);
        k_gates<<<dim3(8, 16), 256>>>(wih);
        k_update<<<128, 128>>>(whh, bih, bhh);
    }
    k_copyout<<<32, 512>>>(out);
}

// round 2
// speedup vs baseline: 1.0007x; 1.0007x over previous
#include <cuda_runtime.h>
#include <math.h>

#define BSZ   128
#define NIMG  256
#define CH    64
#define NPX   4096      // 64*64
#define HID   128

// ---------------- scratch (device globals; no allocation) ----------------
__device__ float g_feat1[NIMG * CH * NPX];   // conv1 out, later final features
__device__ float g_feat2[NIMG * CH * NPX];   // conv2 out
__device__ float g_bnab[2][2][64][2];        // [stage][group][c][{scale,shift}]
__device__ float g_Hx[BSZ * HID];
__device__ float g_Cx[BSZ * HID];
__device__ float g_Fh[BSZ * 8 * 64];
__device__ float g_Fw[BSZ * 8 * 64];
__device__ float g_flat[BSZ * 4096];
__device__ float g_gatesP[16 * BSZ * 512];   // split-K partials

// ---------------- init ----------------
__global__ void k_zero() {
    int i = blockIdx.x * blockDim.x + threadIdx.x;
    if (i < BSZ * HID) { g_Hx[i] = 0.f; g_Cx[i] = 0.f; }
}

// ---------------- conv1: 1 -> 64, 3x3 SAME, + bias ----------------
__global__ __launch_bounds__(256) void k_conv1(const float* __restrict__ img,
                                               const float* __restrict__ w1,
                                               const float* __restrict__ b1) {
    int n = blockIdx.x;            // 0..255
    __shared__ float s[66 * 66];
    __shared__ float ws[64 * 9];
    __shared__ float bs[64];
    int tid = threadIdx.x;

    for (int e = tid; e < 66 * 66; e += 256) s[e] = 0.f;
    for (int e = tid; e < 576; e += 256) ws[e] = w1[e];
    if (tid < 64) bs[tid] = b1[tid];
    __syncthreads();
    const float* ip = img + (size_t)n * NPX;
    for (int e = tid; e < NPX; e += 256) {
        int y = e >> 6, x = e & 63;
        s[(y + 1) * 66 + (x + 1)] = ip[e];
    }
    __syncthreads();

    float* op = g_feat1 + (size_t)n * CH * NPX;
    for (int c0 = 0; c0 < 64; c0 += 4) {
        float wr[36], bb[4];
        #pragma unroll
        for (int cc = 0; cc < 4; cc++) {
            bb[cc] = bs[c0 + cc];
            #pragma unroll
            for (int q = 0; q < 9; q++) wr[cc * 9 + q] = ws[(c0 + cc) * 9 + q];
        }
        for (int k = 0; k < 16; k++) {
            int p = tid + 256 * k;
            int y = p >> 6, x = p & 63;
            float nb[9];
            #pragma unroll
            for (int dy = 0; dy < 3; dy++)
                #pragma unroll
                for (int dx = 0; dx < 3; dx++)
                    nb[dy * 3 + dx] = s[(y + dy) * 66 + x + dx];
            #pragma unroll
            for (int cc = 0; cc < 4; cc++) {
                float a = bb[cc];
                #pragma unroll
                for (int q = 0; q < 9; q++) a = fmaf(wr[cc * 9 + q], nb[q], a);
                op[(size_t)(c0 + cc) * NPX + p] = a;
            }
        }
    }
}

// ---------------- BN stats (deterministic, no atomics) ----------------
// block = (group g, channel c): reduce over 128 images * 4096 px
__global__ __launch_bounds__(256) void k_bnstats(const float* __restrict__ gamma,
                                                 const float* __restrict__ beta,
                                                 int stage) {
    const float* src = stage ? g_feat2 : g_feat1;
    int g = blockIdx.x >> 6, c = blockIdx.x & 63;
    int tid = threadIdx.x;
    float s = 0.f, q = 0.f;
    for (int b = 0; b < 128; b++) {
        const float* p = src + ((size_t)(2 * b + g) * CH + c) * NPX;
        for (int e = tid; e < NPX; e += 256) { float v = p[e]; s += v; q += v * v; }
    }
    __shared__ float rs[256], rq[256];
    rs[tid] = s; rq[tid] = q; __syncthreads();
    for (int st = 128; st > 0; st >>= 1) {
        if (tid < st) { rs[tid] += rs[tid + st]; rq[tid] += rq[tid + st]; }
        __syncthreads();
    }
    if (tid == 0) {
        float mean = rs[0] * (1.f / 524288.f);
        float var  = rq[0] * (1.f / 524288.f) - mean * mean;
        float a = gamma[c] * rsqrtf(var + 1e-5f);
        g_bnab[stage][g][c][0] = a;
        g_bnab[stage][g][c][1] = beta[c] - mean * a;
    }
}

// ---------------- conv2: 64 -> 64, input = relu(bn1(feat1)) on the fly ----------------
// block: one image n, 4-row x 64-col pixel tile, all 64 co.
// 256 thr = 8 co-thr x 32 px-thr ; per-thread 8co x 8px register tile.
__global__ __launch_bounds__(256, 2) void k_conv2(const float* __restrict__ w2,
                                                  const float* __restrict__ b2) {
    __shared__ __align__(16) float in_s[8][6][72];
    __shared__ float w_s[64][76];
    __shared__ float ab_s[64][2];

    int n  = blockIdx.x >> 4;
    int y0 = (blockIdx.x & 15) * 4;
    int g  = n & 1;
    int tid = threadIdx.x;
    int pxthr = tid & 31, cothr = tid >> 5;
    int r = pxthr >> 3, tcol = (pxthr & 7) * 8;
    int co0 = cothr * 8;

    if (tid < 128) ab_s[tid >> 1][tid & 1] = g_bnab[0][g][tid >> 1][tid & 1];
    __syncthreads();

    float acc[8][8];
    #pragma unroll
    for (int j = 0; j < 8; j++)
        #pragma unroll
        for (int p = 0; p < 8; p++) acc[j][p] = 0.f;

    const float* f1 = g_feat1 + (size_t)n * CH * NPX;

    for (int ci0 = 0; ci0 < 64; ci0 += 8) {
        // fill input tile (BN+ReLU applied, zero pad)
        for (int e = tid; e < 8 * 6 * 72; e += 256) {
            int ciL = e / 432; int rem = e - ciL * 432;
            int row = rem / 72; int col = rem - row * 72;
            int y = y0 - 1 + row; int x = col - 1;
            float v = 0.f;
            if (y >= 0 && y < 64 && x >= 0 && x < 64) {
                float t = f1[(size_t)(ci0 + ciL) * NPX + y * 64 + x];
                v = fmaxf(fmaf(ab_s[ci0 + ciL][0], t, ab_s[ci0 + ciL][1]), 0.f);
            }
            in_s[ciL][row][col] = v;
        }
        // fill weight tile: w_s[co][kk], kk = ciL*9 + dy*3 + dx
        for (int e = tid; e < 64 * 72; e += 256) {
            int co = e / 72; int kk = e - co * 72;
            w_s[co][kk] = w2[(size_t)co * 576 + ci0 * 9 + kk];
        }
        __syncthreads();

        for (int ciL = 0; ciL < 8; ciL++) {
            #pragma unroll
            for (int dy = 0; dy < 3; dy++) {
                const float4* bp = (const float4*)&in_s[ciL][r + dy][tcol];
                float4 v0 = bp[0], v1 = bp[1], v2 = bp[2];
                float bseg[12] = {v0.x, v0.y, v0.z, v0.w, v1.x, v1.y, v1.z, v1.w,
                                  v2.x, v2.y, v2.z, v2.w};
                #pragma unroll
                for (int dx = 0; dx < 3; dx++) {
                    int kk = ciL * 9 + dy * 3 + dx;
                    float a[8];
                    #pragma unroll
                    for (int j = 0; j < 8; j++) a[j] = w_s[co0 + j][kk];
                    #pragma unroll
                    for (int j = 0; j < 8; j++)
                        #pragma unroll
                        for (int p = 0; p < 8; p++)
                            acc[j][p] = fmaf(a[j], bseg[p + dx], acc[j][p]);
                }
            }
        }
        __syncthreads();
    }

    float* f2 = g_feat2 + (size_t)n * CH * NPX + (size_t)(y0 + r) * 64 + tcol;
    #pragma unroll
    for (int j = 0; j < 8; j++) {
        float bias = b2[co0 + j];
        float4 o0 = make_float4(acc[j][0] + bias, acc[j][1] + bias,
                                acc[j][2] + bias, acc[j][3] + bias);
        float4 o1 = make_float4(acc[j][4] + bias, acc[j][5] + bias,
                                acc[j][6] + bias, acc[j][7] + bias);
        *(float4*)(f2 + (size_t)(co0 + j) * NPX)     = o0;
        *(float4*)(f2 + (size_t)(co0 + j) * NPX + 4) = o1;
    }
}

// ---------------- bn2 + residual(+orig image broadcast) + relu ----------------
__global__ __launch_bounds__(256) void k_residual(const float* __restrict__ img) {
    size_t e = ((size_t)blockIdx.x * 256 + threadIdx.x) * 4;
    int n = (int)(e >> 18);            // / 262144
    int c = (int)((e >> 12) & 63);
    int p = (int)(e & 4095);
    int g = n & 1;
    float a = g_bnab[1][g][c][0], b = g_bnab[1][g][c][1];
    float4 v = *(const float4*)(g_feat2 + e);
    float4 x = *(const float4*)(img + (size_t)n * NPX + p);
    float4 o;
    o.x = fmaxf(fmaf(a, v.x, b) + x.x, 0.f);
    o.y = fmaxf(fmaf(a, v.y, b) + x.y, 0.f);
    o.z = fmaxf(fmaf(a, v.z, b) + x.z, 0.f);
    o.w = fmaxf(fmaf(a, v.w, b) + x.w, 0.f);
    *(float4*)(g_feat1 + e) = o;
}

// ---------------- glimpser linear + Cauchy filterbanks ----------------
__global__ __launch_bounds__(64) void k_filters(const float* __restrict__ gw,
                                                const float* __restrict__ gb) {
    int b = blockIdx.x, tid = threadIdx.x;            // 64 threads
    __shared__ float red[64];
    __shared__ float gp_s[3];
    __shared__ float ps[2][8];
    const float* hx = g_Hx + b * HID;

    for (int rix = 0; rix < 3; rix++) {
        float s = hx[tid] * gw[rix * 128 + tid] + hx[tid + 64] * gw[rix * 128 + tid + 64];
        red[tid] = s; __syncthreads();
        for (int st = 32; st > 0; st >>= 1) {
            if (tid < st) red[tid] += red[tid + st];
            __syncthreads();
        }
        if (tid == 0) gp_s[rix] = tanhf(red[0] + gb[rix]);
        __syncthreads();
    }

    float d = gp_s[2];
    float delta = 8.f * (1.f - fabsf(d));
    float gamma = expf(1.f - 2.f * fabsf(d));
    float inv_g = 1.f / gamma;
    float fi = (float)tid;
    int lane = tid & 31, wrp = tid >> 5;

    for (int fs = 0; fs < 2; fs++) {
        float center = 31.5f * (gp_s[fs] + 1.f);
        float f[8];
        #pragma unroll
        for (int gg = 0; gg < 8; gg++) {
            float gpos = center + delta * ((float)gg - 3.5f);
            float u = (fi - gpos) * inv_g;
            f[gg] = 1.f / (3.14159265358979323846f * gamma * (1.f + u * u));
        }
        #pragma unroll
        for (int gg = 0; gg < 8; gg++) {
            float s = f[gg];
            for (int off = 16; off > 0; off >>= 1) s += __shfl_down_sync(0xffffffffu, s, off);
            if (lane == 0) ps[wrp][gg] = s;
        }
        __syncthreads();
        float* out = (fs ? g_Fw : g_Fh) + b * 512;
        #pragma unroll
        for (int gg = 0; gg < 8; gg++) {
            float sum = ps[0][gg] + ps[1][gg];
            out[gg * 64 + tid] = f[gg] / (sum + 1e-4f);
        }
        __syncthreads();
    }
}

// ---------------- glimpse: gl = Fh * img * Fw^T, per channel ----------------
// grid 256 = (b, half-of-channels). thread: (c_local 0..15, j0 = 4*(tid&15))
__global__ __launch_bounds__(256) void k_glimpse(int par) {
    int b = blockIdx.x >> 1, half = blockIdx.x & 1;
    int n = 2 * b + par;
    int tid = threadIdx.x;
    int cl = tid >> 4, j0 = (tid & 15) * 4;

    __shared__ float Fh_s[512], Fw_s[512];
    __shared__ __align__(16) float t_s[16][8][64];

    for (int e = tid; e < 512; e += 256) { Fh_s[e] = g_Fh[b * 512 + e]; Fw_s[e] = g_Fw[b * 512 + e]; }
    __syncthreads();

    for (int cb = 0; cb < 2; cb++) {
        int c = half * 32 + cb * 16 + cl;
        const float* ip = g_feat1 + ((size_t)n * CH + c) * NPX;
        float acc[8][4];
        #pragma unroll
        for (int gg = 0; gg < 8; gg++)
            #pragma unroll
            for (int q = 0; q < 4; q++) acc[gg][q] = 0.f;

        #pragma unroll 4
        for (int i = 0; i < 64; i++) {
            float4 v = *(const float4*)(ip + i * 64 + j0);
            #pragma unroll
            for (int gg = 0; gg < 8; gg++) {
                float fh = Fh_s[gg * 64 + i];
                acc[gg][0] = fmaf(fh, v.x, acc[gg][0]);
                acc[gg][1] = fmaf(fh, v.y, acc[gg][1]);
                acc[gg][2] = fmaf(fh, v.z, acc[gg][2]);
                acc[gg][3] = fmaf(fh, v.w, acc[gg][3]);
            }
        }
        #pragma unroll
        for (int gg = 0; gg < 8; gg++)
            *(float4*)&t_s[cl][gg][j0] = make_float4(acc[gg][0], acc[gg][1], acc[gg][2], acc[gg][3]);
        __syncthreads();

        // gl[c][g][w] = sum_j t[c][g][j] * Fw[w][j] ; 1024 outputs, 4/thread
        #pragma unroll
        for (int k = 0; k < 4; k++) {
            int o = tid + 256 * k;
            int cc = o >> 6, gg = (o >> 3) & 7, w = o & 7;
            float s = 0.f;
            #pragma unroll 8
            for (int jj = 0; jj < 64; jj++) s = fmaf(t_s[cc][gg][jj], Fw_s[w * 64 + jj], s);
            int cglob = half * 32 + cb * 16 + cc;
            g_flat[b * 4096 + cglob * 64 + gg * 8 + w] = s;
        }
        __syncthreads();
    }
}

// ---------------- LSTM gates GEMM: gatesP[ks] = flat_chunk @ Wih_chunk^T ----------------
// grid (8 N-tiles, 16 K-splits); block tile M=128, N=64, K=256
__global__ __launch_bounds__(256) void k_gates(const float* __restrict__ wih) {
    __shared__ __align__(16) float A_s[16][132];
    __shared__ __align__(16) float B_s[16][68];
    int tid = threadIdx.x;
    int mt = tid & 15, nt = tid >> 4;
    int r0 = blockIdx.x * 64;
    int kbase = blockIdx.y * 256;

    float acc[8][4];
    #pragma unroll
    for (int i = 0; i < 8; i++)
        #pragma unroll
        for (int j = 0; j < 4; j++) acc[i][j] = 0.f;

    for (int k0 = 0; k0 < 256; k0 += 16) {
        for (int e = tid; e < 2048; e += 256) {
            int bb = e >> 4, kk = e & 15;
            A_s[kk][bb] = g_flat[bb * 4096 + kbase + k0 + kk];
        }
        for (int e = tid; e < 1024; e += 256) {
            int rr = e >> 4, kk = e & 15;
            B_s[kk][rr] = wih[(size_t)(r0 + rr) * 4096 + kbase + k0 + kk];
        }
        __syncthreads();
        #pragma unroll
        for (int kk = 0; kk < 16; kk++) {
            float4 a0 = *(const float4*)&A_s[kk][mt * 8];
            float4 a1 = *(const float4*)&A_s[kk][mt * 8 + 4];
            float4 bv = *(const float4*)&B_s[kk][nt * 4];
            float a[8] = {a0.x, a0.y, a0.z, a0.w, a1.x, a1.y, a1.z, a1.w};
            float bb[4] = {bv.x, bv.y, bv.z, bv.w};
            #pragma unroll
            for (int i = 0; i < 8; i++)
                #pragma unroll
                for (int j = 0; j < 4; j++)
                    acc[i][j] = fmaf(a[i], bb[j], acc[i][j]);
        }
        __syncthreads();
    }
    #pragma unroll
    for (int i = 0; i < 8; i++)
        #pragma unroll
        for (int j = 0; j < 4; j++)
            g_gatesP[((size_t)blockIdx.y * 128 + mt * 8 + i) * 512 + r0 + nt * 4 + j] = acc[i][j];
}

// ---------------- LSTM reduce + Hx@Whh^T + pointwise update ----------------
__global__ __launch_bounds__(128) void k_update(const float* __restrict__ whh,
                                                const float* __restrict__ bih,
                                                const float* __restrict__ bhh) {
    int b = blockIdx.x, j = threadIdx.x;
    __shared__ float hx_s[128];
    hx_s[j] = g_Hx[b * 128 + j];
    __syncthreads();
    float gate[4];
    #pragma unroll
    for (int q = 0; q < 4; q++) {
        int rr = q * 128 + j;
        float s = bih[rr] + bhh[rr];
        #pragma unroll
        for (int ks = 0; ks < 16; ks++) s += g_gatesP[((size_t)ks * 128 + b) * 512 + rr];
        const float* w = whh + (size_t)rr * 128;
        float s2 = 0.f;
        #pragma unroll 8
        for (int h = 0; h < 128; h++) s2 = fmaf(hx_s[h], w[h], s2);
        gate[q] = s + s2;
    }
    float ig = 1.f / (1.f + expf(-gate[0]));
    float fg = 1.f / (1.f + expf(-gate[1]));
    float gg = tanhf(gate[2]);
    float og = 1.f / (1.f + expf(-gate[3]));
    float cx = fg * g_Cx[b * 128 + j] + ig * gg;
    g_Cx[b * 128 + j] = cx;
    g_Hx[b * 128 + j] = og * tanhf(cx);
}

__global__ void k_copyout(float* __restrict__ out) {
    int i = blockIdx.x * blockDim.x + threadIdx.x;
    if (i < BSZ * HID) out[i] = g_Hx[i];
}

// ---------------- launch ----------------
extern "C" void kernel_launch(void* const* d_in, const int* in_sizes, int n_in,
                              void* d_out, int out_size) {
    const float* img  = (const float*)d_in[0];
    const float* c1w  = (const float*)d_in[1];
    const float* c1b  = (const float*)d_in[2];
    const float* bn1g = (const float*)d_in[3];
    const float* bn1b = (const float*)d_in[4];
    const float* c2w  = (const float*)d_in[5];
    const float* c2b  = (const float*)d_in[6];
    const float* bn2g = (const float*)d_in[7];
    const float* bn2b = (const float*)d_in[8];
    const float* wih  = (const float*)d_in[9];
    const float* whh  = (const float*)d_in[10];
    const float* bih  = (const float*)d_in[11];
    const float* bhh  = (const float*)d_in[12];
    const float* gw   = (const float*)d_in[13];
    const float* gb   = (const float*)d_in[14];
    float* out = (float*)d_out;

    k_zero<<<32, 512>>>();
    k_conv1<<<256, 256>>>(img, c1w, c1b);
    k_bnstats<<<128, 256>>>(bn1g, bn1b, 0);
    k_conv2<<<4096, 256>>>(c2w, c2b);
    k_bnstats<<<128, 256>>>(bn2g, bn2b, 1);
    k_residual<<<65536, 256>>>(img);

    for (int turn = 0; turn < 16; ++turn) {
        int par = (turn & 1) ? 0 : 1;   // even turn -> test (pair 1), odd -> support (pair 0)
        k_filters<<<128, 64>>>(gw, gb);
        k_glimpse<<<256, 256>>>(par);
        k_gates<<<dim3(8, 16), 256>>>(wih);
        k_update<<<128, 128>>>(whh, bih, bhh);
    }
    k_copyout<<<32, 512>>>(out);
}

// round 3
// speedup vs baseline: 1.0806x; 1.0799x over previous
#include <cuda_runtime.h>
#include <math.h>

#define BSZ   128
#define NIMG  256
#define CH    64
#define NPX   4096      // 64*64
#define HID   128

// ---------------- scratch (device globals; no allocation) ----------------
__device__ float g_feat1[NIMG * CH * NPX];   // conv1 out, later final features
__device__ float g_feat2[NIMG * CH * NPX];   // conv2 out
__device__ float g_bnab[2][2][64][2];        // [stage][group][c][{scale,shift}]
__device__ float g_Hx[BSZ * HID];
__device__ float g_Cx[BSZ * HID];
__device__ float g_flat[BSZ * 4096];
__device__ float g_gatesP[16 * BSZ * 512];   // split-K partials
__device__ float g_w2t[576 * 64];            // conv2 weights, k-major
__device__ float g_wihT[4096 * 512];         // wih transposed, k-major
__device__ float g_whhT[128 * 512];          // whh transposed

// ---------------- init ----------------
__global__ void k_zero() {
    int i = blockIdx.x * blockDim.x + threadIdx.x;
    if (i < BSZ * HID) { g_Hx[i] = 0.f; g_Cx[i] = 0.f; }
}

// ---------------- one-time weight transposes ----------------
__global__ void k_prep_w2t(const float* __restrict__ w2) {
    int idx = blockIdx.x * 256 + threadIdx.x;
    if (idx < 576 * 64) {
        int co = idx & 63, k = idx >> 6;
        g_w2t[(size_t)k * 64 + co] = w2[(size_t)co * 576 + k];
    }
}

__global__ void k_prep_wihT(const float* __restrict__ wih) {
    __shared__ float s[32][33];
    int kt = blockIdx.x * 32, rt = blockIdx.y * 32;
    int tx = threadIdx.x & 31, ty = threadIdx.x >> 5;  // 8 rows of 32
    #pragma unroll
    for (int i = 0; i < 32; i += 8)
        s[ty + i][tx] = wih[(size_t)(rt + ty + i) * 4096 + kt + tx];  // s[r][k]
    __syncthreads();
    #pragma unroll
    for (int i = 0; i < 32; i += 8)
        g_wihT[(size_t)(kt + ty + i) * 512 + rt + tx] = s[tx][ty + i];
}

__global__ void k_prep_whhT(const float* __restrict__ whh) {
    int idx = blockIdx.x * 512 + threadIdx.x;
    if (idx < 128 * 512) {
        int h = idx >> 9, rr = idx & 511;
        g_whhT[h * 512 + rr] = whh[(size_t)rr * 128 + h];
    }
}

// ---------------- conv1: 1 -> 64, 3x3 SAME, + bias ----------------
__global__ __launch_bounds__(256) void k_conv1(const float* __restrict__ img,
                                               const float* __restrict__ w1,
                                               const float* __restrict__ b1) {
    int n = blockIdx.x;            // 0..255
    __shared__ float s[66 * 66];
    __shared__ float ws[64 * 9];
    __shared__ float bs[64];
    int tid = threadIdx.x;

    for (int e = tid; e < 66 * 66; e += 256) s[e] = 0.f;
    for (int e = tid; e < 576; e += 256) ws[e] = w1[e];
    if (tid < 64) bs[tid] = b1[tid];
    __syncthreads();
    const float* ip = img + (size_t)n * NPX;
    for (int e = tid; e < NPX; e += 256) {
        int y = e >> 6, x = e & 63;
        s[(y + 1) * 66 + (x + 1)] = ip[e];
    }
    __syncthreads();

    float* op = g_feat1 + (size_t)n * CH * NPX;
    for (int c0 = 0; c0 < 64; c0 += 4) {
        float wr[36], bb[4];
        #pragma unroll
        for (int cc = 0; cc < 4; cc++) {
            bb[cc] = bs[c0 + cc];
            #pragma unroll
            for (int q = 0; q < 9; q++) wr[cc * 9 + q] = ws[(c0 + cc) * 9 + q];
        }
        for (int k = 0; k < 16; k++) {
            int p = tid + 256 * k;
            int y = p >> 6, x = p & 63;
            float nb[9];
            #pragma unroll
            for (int dy = 0; dy < 3; dy++)
                #pragma unroll
                for (int dx = 0; dx < 3; dx++)
                    nb[dy * 3 + dx] = s[(y + dy) * 66 + x + dx];
            #pragma unroll
            for (int cc = 0; cc < 4; cc++) {
                float a = bb[cc];
                #pragma unroll
                for (int q = 0; q < 9; q++) a = fmaf(wr[cc * 9 + q], nb[q], a);
                op[(size_t)(c0 + cc) * NPX + p] = a;
            }
        }
    }
}

// ---------------- BN stats (deterministic, no atomics) ----------------
__global__ __launch_bounds__(256) void k_bnstats(const float* __restrict__ gamma,
                                                 const float* __restrict__ beta,
                                                 int stage) {
    const float* src = stage ? g_feat2 : g_feat1;
    int g = blockIdx.x >> 6, c = blockIdx.x & 63;
    int tid = threadIdx.x;
    float s = 0.f, q = 0.f;
    for (int b = 0; b < 128; b++) {
        const float* p = src + ((size_t)(2 * b + g) * CH + c) * NPX;
        for (int e = tid; e < NPX; e += 256) { float v = p[e]; s += v; q += v * v; }
    }
    __shared__ float rs[256], rq[256];
    rs[tid] = s; rq[tid] = q; __syncthreads();
    for (int st = 128; st > 0; st >>= 1) {
        if (tid < st) { rs[tid] += rs[tid + st]; rq[tid] += rq[tid + st]; }
        __syncthreads();
    }
    if (tid == 0) {
        float mean = rs[0] * (1.f / 524288.f);
        float var  = rq[0] * (1.f / 524288.f) - mean * mean;
        float a = gamma[c] * rsqrtf(var + 1e-5f);
        g_bnab[stage][g][c][0] = a;
        g_bnab[stage][g][c][1] = beta[c] - mean * a;
    }
}

// ---------------- conv2: 64 -> 64, input = relu(bn1(feat1)) on the fly ----------------
// block: one image n, 4-row x 64-col pixel tile, all 64 co.
// 256 thr = 8 co-thr x 32 px-thr ; per-thread 8co x 8px register tile.
// weights prepared k-major in g_w2t: w2t[k][co], k = ci*9 + dy*3 + dx
__global__ __launch_bounds__(256, 2) void k_conv2(const float* __restrict__ b2) {
    __shared__ __align__(16) float in_s[8][6][72];
    __shared__ __align__(16) float w_s[72][64];
    __shared__ float ab_s[64][2];

    int n  = blockIdx.x >> 4;
    int y0 = (blockIdx.x & 15) * 4;
    int g  = n & 1;
    int tid = threadIdx.x;
    int pxthr = tid & 31, cothr = tid >> 5;
    int r = pxthr >> 3, tcol = (pxthr & 7) * 8;
    int co0 = cothr * 8;

    if (tid < 128) ab_s[tid >> 1][tid & 1] = g_bnab[0][g][tid >> 1][tid & 1];
    __syncthreads();

    float acc[8][8];
    #pragma unroll
    for (int j = 0; j < 8; j++)
        #pragma unroll
        for (int p = 0; p < 8; p++) acc[j][p] = 0.f;

    const float* f1 = g_feat1 + (size_t)n * CH * NPX;

    for (int ci0 = 0; ci0 < 64; ci0 += 8) {
        // fill input tile (BN+ReLU applied, zero pad)
        for (int e = tid; e < 8 * 6 * 72; e += 256) {
            int ciL = e / 432; int rem = e - ciL * 432;
            int row = rem / 72; int col = rem - row * 72;
            int y = y0 - 1 + row; int x = col - 1;
            float v = 0.f;
            if (y >= 0 && y < 64 && x >= 0 && x < 64) {
                float t = f1[(size_t)(ci0 + ciL) * NPX + y * 64 + x];
                v = fmaxf(fmaf(ab_s[ci0 + ciL][0], t, ab_s[ci0 + ciL][1]), 0.f);
            }
            in_s[ciL][row][col] = v;
        }
        // fill weight tile: contiguous float4 copy (72 kk rows x 64 co)
        {
            const float4* src = (const float4*)(g_w2t + (size_t)ci0 * 9 * 64);
            float4* dst = (float4*)&w_s[0][0];
            for (int e = tid; e < 1152; e += 256) dst[e] = src[e];
        }
        __syncthreads();

        #pragma unroll
        for (int ciL = 0; ciL < 8; ciL++) {
            #pragma unroll
            for (int dy = 0; dy < 3; dy++) {
                const float4* bp = (const float4*)&in_s[ciL][r + dy][tcol];
                float4 v0 = bp[0], v1 = bp[1], v2 = bp[2];
                float bseg[12] = {v0.x, v0.y, v0.z, v0.w, v1.x, v1.y, v1.z, v1.w,
                                  v2.x, v2.y, v2.z, v2.w};
                #pragma unroll
                for (int dx = 0; dx < 3; dx++) {
                    int kk = ciL * 9 + dy * 3 + dx;
                    const float4* wp = (const float4*)&w_s[kk][co0];  // warp-broadcast
                    float4 w0 = wp[0], w1 = wp[1];
                    float a[8] = {w0.x, w0.y, w0.z, w0.w, w1.x, w1.y, w1.z, w1.w};
                    #pragma unroll
                    for (int j = 0; j < 8; j++)
                        #pragma unroll
                        for (int p = 0; p < 8; p++)
                            acc[j][p] = fmaf(a[j], bseg[p + dx], acc[j][p]);
                }
            }
        }
        __syncthreads();
    }

    float* f2 = g_feat2 + (size_t)n * CH * NPX + (size_t)(y0 + r) * 64 + tcol;
    #pragma unroll
    for (int j = 0; j < 8; j++) {
        float bias = b2[co0 + j];
        float4 o0 = make_float4(acc[j][0] + bias, acc[j][1] + bias,
                                acc[j][2] + bias, acc[j][3] + bias);
        float4 o1 = make_float4(acc[j][4] + bias, acc[j][5] + bias,
                                acc[j][6] + bias, acc[j][7] + bias);
        *(float4*)(f2 + (size_t)(co0 + j) * NPX)     = o0;
        *(float4*)(f2 + (size_t)(co0 + j) * NPX + 4) = o1;
    }
}

// ---------------- bn2 + residual(+orig image broadcast) + relu ----------------
__global__ __launch_bounds__(256) void k_residual(const float* __restrict__ img) {
    size_t e = ((size_t)blockIdx.x * 256 + threadIdx.x) * 4;
    int n = (int)(e >> 18);
    int c = (int)((e >> 12) & 63);
    int p = (int)(e & 4095);
    int g = n & 1;
    float a = g_bnab[1][g][c][0], b = g_bnab[1][g][c][1];
    float4 v = *(const float4*)(g_feat2 + e);
    float4 x = *(const float4*)(img + (size_t)n * NPX + p);
    float4 o;
    o.x = fmaxf(fmaf(a, v.x, b) + x.x, 0.f);
    o.y = fmaxf(fmaf(a, v.y, b) + x.y, 0.f);
    o.z = fmaxf(fmaf(a, v.z, b) + x.z, 0.f);
    o.w = fmaxf(fmaf(a, v.w, b) + x.w, 0.f);
    *(float4*)(g_feat1 + e) = o;
}

// ---------------- fused glimpser + filterbank + glimpse contraction ----------------
// grid 512 = (b, quarter of channels). Each block recomputes Fh/Fw for its b.
__global__ __launch_bounds__(256) void k_glimpse(const float* __restrict__ gw,
                                                 const float* __restrict__ gb, int par) {
    int b = blockIdx.x >> 2, q = blockIdx.x & 3;
    int n = 2 * b + par;
    int tid = threadIdx.x;

    __shared__ float gp_s[3];
    __shared__ float ps[2][2][8];
    __shared__ float Fh_s[8][66], Fw_s[8][66];
    __shared__ float t_s[16][8][66];

    // glimpser linear: warp 0
    if (tid < 32) {
        const float* hx = g_Hx + b * HID;
        float h0 = hx[tid], h1 = hx[tid + 32], h2 = hx[tid + 64], h3 = hx[tid + 96];
        #pragma unroll
        for (int rix = 0; rix < 3; rix++) {
            const float* w = gw + rix * HID;
            float s = h0 * w[tid] + h1 * w[tid + 32] + h2 * w[tid + 64] + h3 * w[tid + 96];
            for (int off = 16; off > 0; off >>= 1) s += __shfl_down_sync(0xffffffffu, s, off);
            if (tid == 0) gp_s[rix] = tanhf(s + gb[rix]);
        }
    }
    __syncthreads();

    // Cauchy filterbanks: threads 0..127 (fs = tid>>6, i = tid&63)
    float f[8];
    int fs = tid >> 6, fi_i = tid & 63;
    if (tid < 128) {
        float d = gp_s[2];
        float delta = 8.f * (1.f - fabsf(d));
        float gamma = expf(1.f - 2.f * fabsf(d));
        float inv_g = 1.f / gamma;
        float inv_pg = 1.f / (3.14159265358979323846f * gamma);
        float center = 31.5f * (gp_s[fs] + 1.f);
        float fi = (float)fi_i;
        #pragma unroll
        for (int gg = 0; gg < 8; gg++) {
            float gpos = center + delta * ((float)gg - 3.5f);
            float u = (fi - gpos) * inv_g;
            f[gg] = inv_pg / (1.f + u * u);
        }
        int lane = tid & 31, w2i = (tid >> 5) & 1;
        #pragma unroll
        for (int gg = 0; gg < 8; gg++) {
            float s = f[gg];
            for (int off = 16; off > 0; off >>= 1) s += __shfl_down_sync(0xffffffffu, s, off);
            if (lane == 0) ps[fs][w2i][gg] = s;
        }
    }
    __syncthreads();
    if (tid < 128) {
        #pragma unroll
        for (int gg = 0; gg < 8; gg++) {
            float sum = ps[fs][0][gg] + ps[fs][1][gg];
            float v = f[gg] / (sum + 1e-4f);
            if (fs) Fw_s[gg][fi_i] = v; else Fh_s[gg][fi_i] = v;
        }
    }
    __syncthreads();

    // t[c][g][j] = sum_i Fh[g][i] * img[c][i][j]  (16 channels per block)
    int cl = tid >> 4, j0 = (tid & 15) * 4;
    int c = q * 16 + cl;
    const float* ip = g_feat1 + ((size_t)n * CH + c) * NPX;
    float acc[8][4];
    #pragma unroll
    for (int gg = 0; gg < 8; gg++)
        #pragma unroll
        for (int p = 0; p < 4; p++) acc[gg][p] = 0.f;

    #pragma unroll 4
    for (int ii = 0; ii < 64; ii++) {
        float4 v = *(const float4*)(ip + ii * 64 + j0);
        #pragma unroll
        for (int gg = 0; gg < 8; gg++) {
            float fh = Fh_s[gg][ii];
            acc[gg][0] = fmaf(fh, v.x, acc[gg][0]);
            acc[gg][1] = fmaf(fh, v.y, acc[gg][1]);
            acc[gg][2] = fmaf(fh, v.z, acc[gg][2]);
            acc[gg][3] = fmaf(fh, v.w, acc[gg][3]);
        }
    }
    #pragma unroll
    for (int gg = 0; gg < 8; gg++) {
        t_s[cl][gg][j0 + 0] = acc[gg][0];
        t_s[cl][gg][j0 + 1] = acc[gg][1];
        t_s[cl][gg][j0 + 2] = acc[gg][2];
        t_s[cl][gg][j0 + 3] = acc[gg][3];
    }
    __syncthreads();

    // gl[c][g][w] = sum_j t[c][g][j] * Fw[w][j] ; 1024 outputs, 4/thread
    #pragma unroll
    for (int k = 0; k < 4; k++) {
        int o = tid + 256 * k;
        int cc = o >> 6, gg = (o >> 3) & 7, w = o & 7;
        float s = 0.f;
        #pragma unroll 8
        for (int jj = 0; jj < 64; jj++) s = fmaf(t_s[cc][gg][jj], Fw_s[w][jj], s);
        g_flat[b * 4096 + (q * 16 + cc) * 64 + gg * 8 + w] = s;
    }
}

// ---------------- LSTM gates GEMM: gatesP[ks] = flat_chunk @ Wih_chunk^T ----------------
// grid (8 N-tiles, 16 K-splits); block tile M=128, N=64, K=256; B from g_wihT (k-major)
__global__ __launch_bounds__(256) void k_gates() {
    __shared__ __align__(16) float A_s[16][132];
    __shared__ __align__(16) float B_s[16][72];
    int tid = threadIdx.x;
    int mt = tid & 15, nt = tid >> 4;
    int r0 = blockIdx.x * 64;
    int kbase = blockIdx.y * 256;

    float acc[8][4];
    #pragma unroll
    for (int i = 0; i < 8; i++)
        #pragma unroll
        for (int j = 0; j < 4; j++) acc[i][j] = 0.f;

    for (int k0 = 0; k0 < 256; k0 += 16) {
        for (int e = tid; e < 2048; e += 256) {
            int bb = e >> 4, kk = e & 15;
            A_s[kk][bb] = g_flat[bb * 4096 + kbase + k0 + kk];
        }
        {
            int kk = tid >> 4, rr4 = (tid & 15) * 4;
            float4 v = *(const float4*)(g_wihT + (size_t)(kbase + k0 + kk) * 512 + r0 + rr4);
            *(float4*)&B_s[kk][rr4] = v;
        }
        __syncthreads();
        #pragma unroll
        for (int kk = 0; kk < 16; kk++) {
            float4 a0 = *(const float4*)&A_s[kk][mt * 8];
            float4 a1 = *(const float4*)&A_s[kk][mt * 8 + 4];
            float4 bv = *(const float4*)&B_s[kk][nt * 4];
            float a[8] = {a0.x, a0.y, a0.z, a0.w, a1.x, a1.y, a1.z, a1.w};
            float bb[4] = {bv.x, bv.y, bv.z, bv.w};
            #pragma unroll
            for (int i = 0; i < 8; i++)
                #pragma unroll
                for (int j = 0; j < 4; j++)
                    acc[i][j] = fmaf(a[i], bb[j], acc[i][j]);
        }
        __syncthreads();
    }
    #pragma unroll
    for (int i = 0; i < 8; i++)
        #pragma unroll
        for (int j = 0; j < 4; j++)
            g_gatesP[((size_t)blockIdx.y * 128 + mt * 8 + i) * 512 + r0 + nt * 4 + j] = acc[i][j];
}

// ---------------- LSTM reduce + Hx@Whh^T + pointwise update ----------------
__global__ __launch_bounds__(128) void k_update(const float* __restrict__ bih,
                                                const float* __restrict__ bhh) {
    int b = blockIdx.x, j = threadIdx.x;
    __shared__ float hx_s[128];
    hx_s[j] = g_Hx[b * 128 + j];
    __syncthreads();
    float gate[4];
    #pragma unroll
    for (int q = 0; q < 4; q++) {
        int rr = q * 128 + j;
        float s = bih[rr] + bhh[rr];
        #pragma unroll
        for (int ks = 0; ks < 16; ks++) s += g_gatesP[((size_t)ks * 128 + b) * 512 + rr];
        float s2 = 0.f;
        #pragma unroll 8
        for (int h = 0; h < 128; h++) s2 = fmaf(hx_s[h], g_whhT[h * 512 + rr], s2);
        gate[q] = s + s2;
    }
    float ig = 1.f / (1.f + expf(-gate[0]));
    float fg = 1.f / (1.f + expf(-gate[1]));
    float gg = tanhf(gate[2]);
    float og = 1.f / (1.f + expf(-gate[3]));
    float cx = fg * g_Cx[b * 128 + j] + ig * gg;
    g_Cx[b * 128 + j] = cx;
    g_Hx[b * 128 + j] = og * tanhf(cx);
}

__global__ void k_copyout(float* __restrict__ out) {
    int i = blockIdx.x * blockDim.x + threadIdx.x;
    if (i < BSZ * HID) out[i] = g_Hx[i];
}

// ---------------- launch ----------------
extern "C" void kernel_launch(void* const* d_in, const int* in_sizes, int n_in,
                              void* d_out, int out_size) {
    const float* img  = (const float*)d_in[0];
    const float* c1w  = (const float*)d_in[1];
    const float* c1b  = (const float*)d_in[2];
    const float* bn1g = (const float*)d_in[3];
    const float* bn1b = (const float*)d_in[4];
    const float* c2w  = (const float*)d_in[5];
    const float* c2b  = (const float*)d_in[6];
    const float* bn2g = (const float*)d_in[7];
    const float* bn2b = (const float*)d_in[8];
    const float* wih  = (const float*)d_in[9];
    const float* whh  = (const float*)d_in[10];
    const float* bih  = (const float*)d_in[11];
    const float* bhh  = (const float*)d_in[12];
    const float* gw   = (const float*)d_in[13];
    const float* gb   = (const float*)d_in[14];
    float* out = (float*)d_out;

    k_zero<<<32, 512>>>();
    k_prep_w2t<<<144, 256>>>(c2w);
    k_prep_wihT<<<dim3(128, 16), 256>>>(wih);
    k_prep_whhT<<<128, 512>>>(whh);
    k_conv1<<<256, 256>>>(img, c1w, c1b);
    k_bnstats<<<128, 256>>>(bn1g, bn1b, 0);
    k_conv2<<<4096, 256>>>(c2b);
    k_bnstats<<<128, 256>>>(bn2g, bn2b, 1);
    k_residual<<<65536, 256>>>(img);

    for (int turn = 0; turn < 16; ++turn) {
        int par = (turn & 1) ? 0 : 1;   // even turn -> test (pair 1), odd -> support (pair 0)
        k_glimpse<<<512, 256>>>(gw, gb, par);
        k_gates<<<dim3(8, 16), 256>>>();
        k_update<<<128, 128>>>(bih, bhh);
    }
    k_copyout<<<32, 512>>>(out);
}

// round 4
// speedup vs baseline: 1.0811x; 1.0004x over previous
#include <cuda_runtime.h>
#include <math.h>

#define BSZ   128
#define NIMG  256
#define CH    64
#define NPX   4096      // 64*64
#define HID   128

// ---------------- scratch (device globals; no allocation) ----------------
__device__ float g_feat1[NIMG * CH * NPX];   // conv1 out, later final features
__device__ float g_feat2[NIMG * CH * NPX];   // conv2 out
__device__ float g_bnab[2][2][64][2];        // [stage][group][c][{scale,shift}]
__device__ float g_Hx[BSZ * HID];
__device__ float g_Cx[BSZ * HID];
__device__ float g_flat[BSZ * 4096];
__device__ float g_gatesP[16 * BSZ * 512];   // split-K partials
__device__ float g_w2t[576 * 64];            // conv2 weights, k-major
__device__ float g_wihT[4096 * 512];         // wih transposed, k-major
__device__ float g_whhT[128 * 512];          // whh transposed

// ---------------- init ----------------
__global__ void k_zero() {
    int i = blockIdx.x * blockDim.x + threadIdx.x;
    if (i < BSZ * HID) { g_Hx[i] = 0.f; g_Cx[i] = 0.f; }
}

// ---------------- one-time weight transposes ----------------
__global__ void k_prep_w2t(const float* __restrict__ w2) {
    int idx = blockIdx.x * 256 + threadIdx.x;
    if (idx < 576 * 64) {
        int co = idx & 63, k = idx >> 6;
        g_w2t[(size_t)k * 64 + co] = w2[(size_t)co * 576 + k];
    }
}

__global__ void k_prep_wihT(const float* __restrict__ wih) {
    __shared__ float s[32][33];
    int kt = blockIdx.x * 32, rt = blockIdx.y * 32;
    int tx = threadIdx.x & 31, ty = threadIdx.x >> 5;  // 8 rows of 32
    #pragma unroll
    for (int i = 0; i < 32; i += 8)
        s[ty + i][tx] = wih[(size_t)(rt + ty + i) * 4096 + kt + tx];  // s[r][k]
    __syncthreads();
    #pragma unroll
    for (int i = 0; i < 32; i += 8)
        g_wihT[(size_t)(kt + ty + i) * 512 + rt + tx] = s[tx][ty + i];
}

__global__ void k_prep_whhT(const float* __restrict__ whh) {
    int idx = blockIdx.x * 512 + threadIdx.x;
    if (idx < 128 * 512) {
        int h = idx >> 9, rr = idx & 511;
        g_whhT[h * 512 + rr] = whh[(size_t)rr * 128 + h];
    }
}

// ---------------- conv1: 1 -> 64, 3x3 SAME, + bias ----------------
__global__ __launch_bounds__(256) void k_conv1(const float* __restrict__ img,
                                               const float* __restrict__ w1,
                                               const float* __restrict__ b1) {
    int n = blockIdx.x;            // 0..255
    __shared__ float s[66 * 66];
    __shared__ float ws[64 * 9];
    __shared__ float bs[64];
    int tid = threadIdx.x;

    for (int e = tid; e < 66 * 66; e += 256) s[e] = 0.f;
    for (int e = tid; e < 576; e += 256) ws[e] = w1[e];
    if (tid < 64) bs[tid] = b1[tid];
    __syncthreads();
    const float* ip = img + (size_t)n * NPX;
    for (int e = tid; e < NPX; e += 256) {
        int y = e >> 6, x = e & 63;
        s[(y + 1) * 66 + (x + 1)] = ip[e];
    }
    __syncthreads();

    float* op = g_feat1 + (size_t)n * CH * NPX;
    for (int c0 = 0; c0 < 64; c0 += 4) {
        float wr[36], bb[4];
        #pragma unroll
        for (int cc = 0; cc < 4; cc++) {
            bb[cc] = bs[c0 + cc];
            #pragma unroll
            for (int q = 0; q < 9; q++) wr[cc * 9 + q] = ws[(c0 + cc) * 9 + q];
        }
        for (int k = 0; k < 16; k++) {
            int p = tid + 256 * k;
            int y = p >> 6, x = p & 63;
            float nb[9];
            #pragma unroll
            for (int dy = 0; dy < 3; dy++)
                #pragma unroll
                for (int dx = 0; dx < 3; dx++)
                    nb[dy * 3 + dx] = s[(y + dy) * 66 + x + dx];
            #pragma unroll
            for (int cc = 0; cc < 4; cc++) {
                float a = bb[cc];
                #pragma unroll
                for (int q = 0; q < 9; q++) a = fmaf(wr[cc * 9 + q], nb[q], a);
                op[(size_t)(c0 + cc) * NPX + p] = a;
            }
        }
    }
}

// ---------------- BN stats (deterministic, no atomics) ----------------
__global__ __launch_bounds__(256) void k_bnstats(const float* __restrict__ gamma,
                                                 const float* __restrict__ beta,
                                                 int stage) {
    const float* src = stage ? g_feat2 : g_feat1;
    int g = blockIdx.x >> 6, c = blockIdx.x & 63;
    int tid = threadIdx.x;
    float s = 0.f, q = 0.f;
    for (int b = 0; b < 128; b++) {
        const float* p = src + ((size_t)(2 * b + g) * CH + c) * NPX;
        for (int e = tid; e < NPX; e += 256) { float v = p[e]; s += v; q += v * v; }
    }
    __shared__ float rs[256], rq[256];
    rs[tid] = s; rq[tid] = q; __syncthreads();
    for (int st = 128; st > 0; st >>= 1) {
        if (tid < st) { rs[tid] += rs[tid + st]; rq[tid] += rq[tid + st]; }
        __syncthreads();
    }
    if (tid == 0) {
        float mean = rs[0] * (1.f / 524288.f);
        float var  = rq[0] * (1.f / 524288.f) - mean * mean;
        float a = gamma[c] * rsqrtf(var + 1e-5f);
        g_bnab[stage][g][c][0] = a;
        g_bnab[stage][g][c][1] = beta[c] - mean * a;
    }
}

// ---------------- conv2: 64 -> 64, input = relu(bn1(feat1)) on the fly ----------------
// block: one image n, 4-row x 64-col pixel tile, all 64 co.
// 256 thr = 8 co-thr x 32 px-thr ; per-thread 8co x 8px register tile.
// weights prepared k-major in g_w2t: w2t[k][co], k = ci*9 + dy*3 + dx
__global__ __launch_bounds__(256, 2) void k_conv2(const float* __restrict__ b2) {
    __shared__ __align__(16) float in_s[8][6][72];
    __shared__ __align__(16) float w_s[72][64];
    __shared__ float ab_s[64][2];

    int n  = blockIdx.x >> 4;
    int y0 = (blockIdx.x & 15) * 4;
    int g  = n & 1;
    int tid = threadIdx.x;
    int pxthr = tid & 31, cothr = tid >> 5;
    int r = pxthr >> 3, tcol = (pxthr & 7) * 8;
    int co0 = cothr * 8;

    if (tid < 128) ab_s[tid >> 1][tid & 1] = g_bnab[0][g][tid >> 1][tid & 1];
    __syncthreads();

    float acc[8][8];
    #pragma unroll
    for (int j = 0; j < 8; j++)
        #pragma unroll
        for (int p = 0; p < 8; p++) acc[j][p] = 0.f;

    const float* f1 = g_feat1 + (size_t)n * CH * NPX;

    for (int ci0 = 0; ci0 < 64; ci0 += 8) {
        // fill input tile (BN+ReLU applied, zero pad)
        for (int e = tid; e < 8 * 6 * 72; e += 256) {
            int ciL = e / 432; int rem = e - ciL * 432;
            int row = rem / 72; int col = rem - row * 72;
            int y = y0 - 1 + row; int x = col - 1;
            float v = 0.f;
            if (y >= 0 && y < 64 && x >= 0 && x < 64) {
                float t = f1[(size_t)(ci0 + ciL) * NPX + y * 64 + x];
                v = fmaxf(fmaf(ab_s[ci0 + ciL][0], t, ab_s[ci0 + ciL][1]), 0.f);
            }
            in_s[ciL][row][col] = v;
        }
        // fill weight tile: contiguous float4 copy (72 kk rows x 64 co)
        {
            const float4* src = (const float4*)(g_w2t + (size_t)ci0 * 9 * 64);
            float4* dst = (float4*)&w_s[0][0];
            for (int e = tid; e < 1152; e += 256) dst[e] = src[e];
        }
        __syncthreads();

        #pragma unroll
        for (int ciL = 0; ciL < 8; ciL++) {
            #pragma unroll
            for (int dy = 0; dy < 3; dy++) {
                const float4* bp = (const float4*)&in_s[ciL][r + dy][tcol];
                float4 v0 = bp[0], v1 = bp[1], v2 = bp[2];
                float bseg[12] = {v0.x, v0.y, v0.z, v0.w, v1.x, v1.y, v1.z, v1.w,
                                  v2.x, v2.y, v2.z, v2.w};
                #pragma unroll
                for (int dx = 0; dx < 3; dx++) {
                    int kk = ciL * 9 + dy * 3 + dx;
                    const float4* wp = (const float4*)&w_s[kk][co0];  // warp-broadcast
                    float4 w0 = wp[0], w1 = wp[1];
                    float a[8] = {w0.x, w0.y, w0.z, w0.w, w1.x, w1.y, w1.z, w1.w};
                    #pragma unroll
                    for (int j = 0; j < 8; j++)
                        #pragma unroll
                        for (int p = 0; p < 8; p++)
                            acc[j][p] = fmaf(a[j], bseg[p + dx], acc[j][p]);
                }
            }
        }
        __syncthreads();
    }

    float* f2 = g_feat2 + (size_t)n * CH * NPX + (size_t)(y0 + r) * 64 + tcol;
    #pragma unroll
    for (int j = 0; j < 8; j++) {
        float bias = b2[co0 + j];
        float4 o0 = make_float4(acc[j][0] + bias, acc[j][1] + bias,
                                acc[j][2] + bias, acc[j][3] + bias);
        float4 o1 = make_float4(acc[j][4] + bias, acc[j][5] + bias,
                                acc[j][6] + bias, acc[j][7] + bias);
        *(float4*)(f2 + (size_t)(co0 + j) * NPX)     = o0;
        *(float4*)(f2 + (size_t)(co0 + j) * NPX + 4) = o1;
    }
}

// ---------------- bn2 + residual(+orig image broadcast) + relu ----------------
__global__ __launch_bounds__(256) void k_residual(const float* __restrict__ img) {
    size_t e = ((size_t)blockIdx.x * 256 + threadIdx.x) * 4;
    int n = (int)(e >> 18);
    int c = (int)((e >> 12) & 63);
    int p = (int)(e & 4095);
    int g = n & 1;
    float a = g_bnab[1][g][c][0], b = g_bnab[1][g][c][1];
    float4 v = *(const float4*)(g_feat2 + e);
    float4 x = *(const float4*)(img + (size_t)n * NPX + p);
    float4 o;
    o.x = fmaxf(fmaf(a, v.x, b) + x.x, 0.f);
    o.y = fmaxf(fmaf(a, v.y, b) + x.y, 0.f);
    o.z = fmaxf(fmaf(a, v.z, b) + x.z, 0.f);
    o.w = fmaxf(fmaf(a, v.w, b) + x.w, 0.f);
    *(float4*)(g_feat1 + e) = o;
}

// ---------------- fused glimpser + filterbank + glimpse contraction ----------------
// grid 512 = (b, quarter of channels). Each block recomputes Fh/Fw for its b.
__global__ __launch_bounds__(256) void k_glimpse(const float* __restrict__ gw,
                                                 const float* __restrict__ gb, int par) {
    int b = blockIdx.x >> 2, q = blockIdx.x & 3;
    int n = 2 * b + par;
    int tid = threadIdx.x;

    __shared__ float gp_s[3];
    __shared__ float ps[2][2][8];
    __shared__ float Fh_s[8][66], Fw_s[8][66];
    __shared__ float t_s[16][8][66];

    // glimpser linear: warp 0
    if (tid < 32) {
        const float* hx = g_Hx + b * HID;
        float h0 = hx[tid], h1 = hx[tid + 32], h2 = hx[tid + 64], h3 = hx[tid + 96];
        #pragma unroll
        for (int rix = 0; rix < 3; rix++) {
            const float* w = gw + rix * HID;
            float s = h0 * w[tid] + h1 * w[tid + 32] + h2 * w[tid + 64] + h3 * w[tid + 96];
            for (int off = 16; off > 0; off >>= 1) s += __shfl_down_sync(0xffffffffu, s, off);
            if (tid == 0) gp_s[rix] = tanhf(s + gb[rix]);
        }
    }
    __syncthreads();

    // Cauchy filterbanks: threads 0..127 (fs = tid>>6, i = tid&63)
    float f[8];
    int fs = tid >> 6, fi_i = tid & 63;
    if (tid < 128) {
        float d = gp_s[2];
        float delta = 8.f * (1.f - fabsf(d));
        float gamma = expf(1.f - 2.f * fabsf(d));
        float inv_g = 1.f / gamma;
        float inv_pg = 1.f / (3.14159265358979323846f * gamma);
        float center = 31.5f * (gp_s[fs] + 1.f);
        float fi = (float)fi_i;
        #pragma unroll
        for (int gg = 0; gg < 8; gg++) {
            float gpos = center + delta * ((float)gg - 3.5f);
            float u = (fi - gpos) * inv_g;
            f[gg] = inv_pg / (1.f + u * u);
        }
        int lane = tid & 31, w2i = (tid >> 5) & 1;
        #pragma unroll
        for (int gg = 0; gg < 8; gg++) {
            float s = f[gg];
            for (int off = 16; off > 0; off >>= 1) s += __shfl_down_sync(0xffffffffu, s, off);
            if (lane == 0) ps[fs][w2i][gg] = s;
        }
    }
    __syncthreads();
    if (tid < 128) {
        #pragma unroll
        for (int gg = 0; gg < 8; gg++) {
            float sum = ps[fs][0][gg] + ps[fs][1][gg];
            float v = f[gg] / (sum + 1e-4f);
            if (fs) Fw_s[gg][fi_i] = v; else Fh_s[gg][fi_i] = v;
        }
    }
    __syncthreads();

    // t[c][g][j] = sum_i Fh[g][i] * img[c][i][j]  (16 channels per block)
    int cl = tid >> 4, j0 = (tid & 15) * 4;
    int c = q * 16 + cl;
    const float* ip = g_feat1 + ((size_t)n * CH + c) * NPX;
    float acc[8][4];
    #pragma unroll
    for (int gg = 0; gg < 8; gg++)
        #pragma unroll
        for (int p = 0; p < 4; p++) acc[gg][p] = 0.f;

    #pragma unroll 4
    for (int ii = 0; ii < 64; ii++) {
        float4 v = *(const float4*)(ip + ii * 64 + j0);
        #pragma unroll
        for (int gg = 0; gg < 8; gg++) {
            float fh = Fh_s[gg][ii];
            acc[gg][0] = fmaf(fh, v.x, acc[gg][0]);
            acc[gg][1] = fmaf(fh, v.y, acc[gg][1]);
            acc[gg][2] = fmaf(fh, v.z, acc[gg][2]);
            acc[gg][3] = fmaf(fh, v.w, acc[gg][3]);
        }
    }
    #pragma unroll
    for (int gg = 0; gg < 8; gg++) {
        t_s[cl][gg][j0 + 0] = acc[gg][0];
        t_s[cl][gg][j0 + 1] = acc[gg][1];
        t_s[cl][gg][j0 + 2] = acc[gg][2];
        t_s[cl][gg][j0 + 3] = acc[gg][3];
    }
    __syncthreads();

    // gl[c][g][w] = sum_j t[c][g][j] * Fw[w][j] ; 1024 outputs, 4/thread
    #pragma unroll
    for (int k = 0; k < 4; k++) {
        int o = tid + 256 * k;
        int cc = o >> 6, gg = (o >> 3) & 7, w = o & 7;
        float s = 0.f;
        #pragma unroll 8
        for (int jj = 0; jj < 64; jj++) s = fmaf(t_s[cc][gg][jj], Fw_s[w][jj], s);
        g_flat[b * 4096 + (q * 16 + cc) * 64 + gg * 8 + w] = s;
    }
}

// ---------------- LSTM gates GEMM: gatesP[ks] = flat_chunk @ Wih_chunk^T ----------------
// grid (8 N-tiles, 16 K-splits); block tile M=128, N=64, K=256; B from g_wihT (k-major)
__global__ __launch_bounds__(256) void k_gates() {
    __shared__ __align__(16) float A_s[16][132];
    __shared__ __align__(16) float B_s[16][72];
    int tid = threadIdx.x;
    int mt = tid & 15, nt = tid >> 4;
    int r0 = blockIdx.x * 64;
    int kbase = blockIdx.y * 256;

    float acc[8][4];
    #pragma unroll
    for (int i = 0; i < 8; i++)
        #pragma unroll
        for (int j = 0; j < 4; j++) acc[i][j] = 0.f;

    for (int k0 = 0; k0 < 256; k0 += 16) {
        for (int e = tid; e < 2048; e += 256) {
            int bb = e >> 4, kk = e & 15;
            A_s[kk][bb] = g_flat[bb * 4096 + kbase + k0 + kk];
        }
        {
            int kk = tid >> 4, rr4 = (tid & 15) * 4;
            float4 v = *(const float4*)(g_wihT + (size_t)(kbase + k0 + kk) * 512 + r0 + rr4);
            *(float4*)&B_s[kk][rr4] = v;
        }
        __syncthreads();
        #pragma unroll
        for (int kk = 0; kk < 16; kk++) {
            float4 a0 = *(const float4*)&A_s[kk][mt * 8];
            float4 a1 = *(const float4*)&A_s[kk][mt * 8 + 4];
            float4 bv = *(const float4*)&B_s[kk][nt * 4];
            float a[8] = {a0.x, a0.y, a0.z, a0.w, a1.x, a1.y, a1.z, a1.w};
            float bb[4] = {bv.x, bv.y, bv.z, bv.w};
            #pragma unroll
            for (int i = 0; i < 8; i++)
                #pragma unroll
                for (int j = 0; j < 4; j++)
                    acc[i][j] = fmaf(a[i], bb[j], acc[i][j]);
        }
        __syncthreads();
    }
    #pragma unroll
    for (int i = 0; i < 8; i++)
        #pragma unroll
        for (int j = 0; j < 4; j++)
            g_gatesP[((size_t)blockIdx.y * 128 + mt * 8 + i) * 512 + r0 + nt * 4 + j] = acc[i][j];
}

// ---------------- LSTM reduce + Hx@Whh^T + pointwise update ----------------
__global__ __launch_bounds__(128) void k_update(const float* __restrict__ bih,
                                                const float* __restrict__ bhh) {
    int b = blockIdx.x, j = threadIdx.x;
    __shared__ float hx_s[128];
    hx_s[j] = g_Hx[b * 128 + j];
    __syncthreads();
    float gate[4];
    #pragma unroll
    for (int q = 0; q < 4; q++) {
        int rr = q * 128 + j;
        float s = bih[rr] + bhh[rr];
        #pragma unroll
        for (int ks = 0; ks < 16; ks++) s += g_gatesP[((size_t)ks * 128 + b) * 512 + rr];
        float s2 = 0.f;
        #pragma unroll 8
        for (int h = 0; h < 128; h++) s2 = fmaf(hx_s[h], g_whhT[h * 512 + rr], s2);
        gate[q] = s + s2;
    }
    float ig = 1.f / (1.f + expf(-gate[0]));
    float fg = 1.f / (1.f + expf(-gate[1]));
    float gg = tanhf(gate[2]);
    float og = 1.f / (1.f + expf(-gate[3]));
    float cx = fg * g_Cx[b * 128 + j] + ig * gg;
    g_Cx[b * 128 + j] = cx;
    g_Hx[b * 128 + j] = og * tanhf(cx);
}

__global__ void k_copyout(float* __restrict__ out) {
    int i = blockIdx.x * blockDim.x + threadIdx.x;
    if (i < BSZ * HID) out[i] = g_Hx[i];
}

// ---------------- launch ----------------
extern "C" void kernel_launch(void* const* d_in, const int* in_sizes, int n_in,
                              void* d_out, int out_size) {
    const float* img  = (const float*)d_in[0];
    const float* c1w  = (const float*)d_in[1];
    const float* c1b  = (const float*)d_in[2];
    const float* bn1g = (const float*)d_in[3];
    const float* bn1b = (const float*)d_in[4];
    const float* c2w  = (const float*)d_in[5];
    const float* c2b  = (const float*)d_in[6];
    const float* bn2g = (const float*)d_in[7];
    const float* bn2b = (const float*)d_in[8];
    const float* wih  = (const float*)d_in[9];
    const float* whh  = (const float*)d_in[10];
    const float* bih  = (const float*)d_in[11];
    const float* bhh  = (const float*)d_in[12];
    const float* gw   = (const float*)d_in[13];
    const float* gb   = (const float*)d_in[14];
    float* out = (float*)d_out;

    k_zero<<<32, 512>>>();
    k_prep_w2t<<<144, 256>>>(c2w);
    k_prep_wihT<<<dim3(128, 16), 256>>>(wih);
    k_prep_whhT<<<128, 512>>>(whh);
    k_conv1<<<256, 256>>>(img, c1w, c1b);
    k_bnstats<<<128, 256>>>(bn1g, bn1b, 0);
    k_conv2<<<4096, 256>>>(c2b);
    k_bnstats<<<128, 256>>>(bn2g, bn2b, 1);
    k_residual<<<65536, 256>>>(img);

    for (int turn = 0; turn < 16; ++turn) {
        int par = (turn & 1) ? 0 : 1;   // even turn -> test (pair 1), odd -> support (pair 0)
        k_glimpse<<<512, 256>>>(gw, gb, par);
        k_gates<<<dim3(8, 16), 256>>>();
        k_update<<<128, 128>>>(bih, bhh);
    }
    k_copyout<<<32, 512>>>(out);
}

// round 6
// speedup vs baseline: 1.2221x; 1.1305x over previous
#include <cuda_runtime.h>
#include <stdint.h>
#include <math.h>

#define BSZ   128
#define NIMG  256
#define CH    64
#define NPX   4096      // 64*64
#define HID   128

// ---------------- scratch (device globals; no allocation) ----------------
__device__ __align__(16) float g_feat1[NIMG * CH * NPX];   // final features (after residual)
__device__ __align__(16) float g_feat2[NIMG * CH * NPX];   // conv2 out
__device__ __align__(16) float g_feat3[NIMG * CH * NPX];   // relu(bn1(conv1)) = conv2 input
__device__ float g_bnab[2][2][64][2];        // [stage][group][c][{scale,shift}]
__device__ float g_Hx[BSZ * HID];
__device__ float g_Cx[BSZ * HID];
__device__ __align__(16) float g_flat[BSZ * 4096];
__device__ __align__(16) float g_gatesP[16 * BSZ * 512];   // split-K partials
__device__ __align__(16) float g_w2t[576 * 64];            // conv2 weights, k-major
__device__ __align__(16) float g_wihT[4096 * 512];         // wih transposed, k-major
__device__ __align__(16) float g_whhT[128 * 512];          // whh transposed
__device__ float g_c1part[NIMG * 128];       // [n][c*2+{s,q}] conv1 stats partials
__device__ float g_c2part[4096 * 128];       // [block][c*2+{s,q}] conv2 stats partials

// ---------------- helpers ----------------
__device__ __forceinline__ unsigned s2u(const void* p) {
    unsigned a;
    asm("{ .reg .u64 t; cvta.to.shared.u64 t, %1; cvt.u32.u64 %0, t; }" : "=r"(a) : "l"(p));
    return a;
}
__device__ __forceinline__ void cpa4(unsigned dst, const void* src, int sz) {
    asm volatile("cp.async.ca.shared.global [%0],[%1],4,%2;" :: "r"(dst), "l"(src), "r"(sz));
}
__device__ __forceinline__ void cpa16(unsigned dst, const void* src) {
    asm volatile("cp.async.ca.shared.global [%0],[%1],16;" :: "r"(dst), "l"(src));
}

// ---------------- init ----------------
__global__ void k_zero() {
    int i = blockIdx.x * blockDim.x + threadIdx.x;
    if (i < BSZ * HID) { g_Hx[i] = 0.f; g_Cx[i] = 0.f; }
}

// ---------------- one-time weight transposes ----------------
__global__ void k_prep_w2t(const float* __restrict__ w2) {
    int idx = blockIdx.x * 256 + threadIdx.x;
    if (idx < 576 * 64) {
        int co = idx & 63, k = idx >> 6;
        g_w2t[(size_t)k * 64 + co] = w2[(size_t)co * 576 + k];
    }
}

__global__ void k_prep_wihT(const float* __restrict__ wih) {
    __shared__ float s[32][33];
    int kt = blockIdx.x * 32, rt = blockIdx.y * 32;
    int tx = threadIdx.x & 31, ty = threadIdx.x >> 5;  // 8 rows of 32
    #pragma unroll
    for (int i = 0; i < 32; i += 8)
        s[ty + i][tx] = wih[(size_t)(rt + ty + i) * 4096 + kt + tx];  // s[r][k]
    __syncthreads();
    #pragma unroll
    for (int i = 0; i < 32; i += 8)
        g_wihT[(size_t)(kt + ty + i) * 512 + rt + tx] = s[tx][ty + i];
}

__global__ void k_prep_whhT(const float* __restrict__ whh) {
    int idx = blockIdx.x * 512 + threadIdx.x;
    if (idx < 128 * 512) {
        int h = idx >> 9, rr = idx & 511;
        g_whhT[h * 512 + rr] = whh[(size_t)rr * 128 + h];
    }
}

// ---------------- conv1: 1 -> 64, 3x3 SAME, + bias ----------------
// mode 0: accumulate per-(n,c) sum/sumsq of conv+bias (NO feature write)
// mode 1: write relu(bn1(conv+bias)) to g_feat3
__global__ __launch_bounds__(256) void k_conv1(const float* __restrict__ img,
                                               const float* __restrict__ w1,
                                               const float* __restrict__ b1,
                                               int mode) {
    int n = blockIdx.x;            // 0..255
    __shared__ float s[66 * 66];
    __shared__ float ws[64 * 9];
    __shared__ float bs[64];
    __shared__ float smr[8][4][2];
    int tid = threadIdx.x;
    int lane = tid & 31, wrp = tid >> 5;
    int g = n & 1;

    for (int e = tid; e < 66 * 66; e += 256) s[e] = 0.f;
    for (int e = tid; e < 576; e += 256) ws[e] = w1[e];
    if (tid < 64) bs[tid] = b1[tid];
    __syncthreads();
    const float* ip = img + (size_t)n * NPX;
    for (int e = tid; e < NPX; e += 256) {
        int y = e >> 6, x = e & 63;
        s[(y + 1) * 66 + (x + 1)] = ip[e];
    }
    __syncthreads();

    float* op = g_feat3 + (size_t)n * CH * NPX;
    for (int c0 = 0; c0 < 64; c0 += 4) {
        float wr[36], bb[4], scl[4], sft[4];
        #pragma unroll
        for (int cc = 0; cc < 4; cc++) {
            bb[cc] = bs[c0 + cc];
            #pragma unroll
            for (int q = 0; q < 9; q++) wr[cc * 9 + q] = ws[(c0 + cc) * 9 + q];
        }
        if (mode) {
            #pragma unroll
            for (int cc = 0; cc < 4; cc++) {
                scl[cc] = g_bnab[0][g][c0 + cc][0];
                sft[cc] = g_bnab[0][g][c0 + cc][1];
            }
        }
        float sc[4] = {0.f, 0.f, 0.f, 0.f}, qc[4] = {0.f, 0.f, 0.f, 0.f};
        for (int k = 0; k < 16; k++) {
            int p = tid + 256 * k;
            int y = p >> 6, x = p & 63;
            float nb[9];
            #pragma unroll
            for (int dy = 0; dy < 3; dy++)
                #pragma unroll
                for (int dx = 0; dx < 3; dx++)
                    nb[dy * 3 + dx] = s[(y + dy) * 66 + x + dx];
            #pragma unroll
            for (int cc = 0; cc < 4; cc++) {
                float a = bb[cc];
                #pragma unroll
                for (int q = 0; q < 9; q++) a = fmaf(wr[cc * 9 + q], nb[q], a);
                if (mode) {
                    op[(size_t)(c0 + cc) * NPX + p] = fmaxf(fmaf(scl[cc], a, sft[cc]), 0.f);
                } else {
                    sc[cc] += a; qc[cc] = fmaf(a, a, qc[cc]);
                }
            }
        }
        if (!mode) {
            #pragma unroll
            for (int cc = 0; cc < 4; cc++) {
                #pragma unroll
                for (int off = 16; off > 0; off >>= 1) {
                    sc[cc] += __shfl_down_sync(0xffffffffu, sc[cc], off);
                    qc[cc] += __shfl_down_sync(0xffffffffu, qc[cc], off);
                }
            }
            if (lane == 0) {
                #pragma unroll
                for (int cc = 0; cc < 4; cc++) { smr[wrp][cc][0] = sc[cc]; smr[wrp][cc][1] = qc[cc]; }
            }
            __syncthreads();
            if (tid < 8) {
                int cc = tid >> 1, sel = tid & 1;
                float t = 0.f;
                #pragma unroll
                for (int ww = 0; ww < 8; ww++) t += smr[ww][cc][sel];
                g_c1part[n * 128 + (c0 + cc) * 2 + sel] = t;
            }
            __syncthreads();
        }
    }
}

// ---------------- bn1 coefficient reduce ----------------
__global__ __launch_bounds__(128) void k_bn1red(const float* __restrict__ gamma,
                                                const float* __restrict__ beta) {
    int g = blockIdx.x >> 6, c = blockIdx.x & 63;
    int b = threadIdx.x;  // 128
    __shared__ float rs[128], rq[128];
    rs[b] = g_c1part[(2 * b + g) * 128 + c * 2];
    rq[b] = g_c1part[(2 * b + g) * 128 + c * 2 + 1];
    __syncthreads();
    for (int st = 64; st > 0; st >>= 1) {
        if (b < st) { rs[b] += rs[b + st]; rq[b] += rq[b + st]; }
        __syncthreads();
    }
    if (b == 0) {
        float mean = rs[0] * (1.f / 524288.f);
        float var  = rq[0] * (1.f / 524288.f) - mean * mean;
        float a = gamma[c] * rsqrtf(var + 1e-5f);
        g_bnab[0][g][c][0] = a;
        g_bnab[0][g][c][1] = beta[c] - mean * a;
    }
}

// ---------------- conv2: 64 -> 64, cp.async double-buffered ----------------
// block: image n, 4-row x 64-col pixel tile, all 64 co.
// 256 thr = 8 co-thr x 32 px-thr ; per-thread 8co x 8px register tile.
// input from g_feat3 (already BN1+ReLU). Writes g_feat2 + BN2 partial stats.
__device__ __forceinline__ void conv2_issue(int n, int y0, int s, int buf,
                                            unsigned in0, unsigned w0, int tid) {
    int ci0 = s * 8;
    const float* f3 = g_feat3 + (size_t)n * CH * NPX;
    #pragma unroll
    for (int k = 0; k < 12; k++) {
        int e = tid + 256 * k;          // e < 3072
        int ciL = e / 384; int rem = e - ciL * 384;
        int row = rem >> 6; int colx = rem & 63;
        int y = y0 - 1 + row;
        int ok = (y >= 0 && y < 64);
        const float* src = f3 + (((size_t)(ci0 + ciL)) << 12) + ((size_t)(ok ? y : 0) << 6) + colx;
        unsigned dst = in0 + (unsigned)buf * 13824u +
                       (unsigned)(((ciL * 6 + row) * 72 + 1 + colx) * 4);
        cpa4(dst, src, ok ? 4 : 0);
    }
    const float* wsrc = g_w2t + (size_t)ci0 * 576;
    #pragma unroll
    for (int k = 0; k < 5; k++) {
        int e = tid + 256 * k;
        if (e < 1152) {
            unsigned dst = w0 + (unsigned)buf * 18432u + (unsigned)(e * 16);
            cpa16(dst, wsrc + e * 4);
        }
    }
}

__global__ __launch_bounds__(256, 2) void k_conv2(const float* __restrict__ b2) {
    __shared__ __align__(16) float in_s[2][3456];   // [buf][(ciL*6+row)*72 + col]
    __shared__ __align__(16) float w_s[2][4608];    // [buf][kk*64 + co]

    int n  = blockIdx.x >> 4;
    int y0 = (blockIdx.x & 15) * 4;
    int tid = threadIdx.x;
    int pxthr = tid & 31, cothr = tid >> 5;
    int r = pxthr >> 3, tcol = (pxthr & 7) * 8;
    int co0 = cothr * 8;
    unsigned in0 = s2u(in_s), w0 = s2u(w_s);

    // zero halo cols (0 and 65..71) of both buffers — written only once
    for (int e = tid; e < 768; e += 256) {
        int buf = e / 384; int rem = e - buf * 384;
        int cir = rem >> 3; int h = rem & 7;
        int col = (h == 0) ? 0 : 64 + h;
        in_s[buf][cir * 72 + col] = 0.f;
    }

    float acc[8][8];
    #pragma unroll
    for (int j = 0; j < 8; j++)
        #pragma unroll
        for (int p = 0; p < 8; p++) acc[j][p] = 0.f;

    conv2_issue(n, y0, 0, 0, in0, w0, tid);
    asm volatile("cp.async.commit_group;");

    for (int s = 0; s < 8; s++) {
        if (s < 7) {
            conv2_issue(n, y0, s + 1, (s + 1) & 1, in0, w0, tid);
            asm volatile("cp.async.commit_group;");
            asm volatile("cp.async.wait_group 1;");
        } else {
            asm volatile("cp.async.wait_group 0;");
        }
        __syncthreads();

        const float* in = in_s[s & 1];
        const float* ws = w_s[s & 1];
        #pragma unroll
        for (int ciL = 0; ciL < 8; ciL++) {
            #pragma unroll
            for (int dy = 0; dy < 3; dy++) {
                const float4* bp = (const float4*)(in + (ciL * 6 + r + dy) * 72 + tcol);
                float4 v0 = bp[0], v1 = bp[1], v2 = bp[2];
                float bseg[12] = {v0.x, v0.y, v0.z, v0.w, v1.x, v1.y, v1.z, v1.w,
                                  v2.x, v2.y, v2.z, v2.w};
                #pragma unroll
                for (int dx = 0; dx < 3; dx++) {
                    int kk = ciL * 9 + dy * 3 + dx;
                    const float4* wp = (const float4*)(ws + kk * 64 + co0);
                    float4 w0v = wp[0], w1v = wp[1];
                    float a[8] = {w0v.x, w0v.y, w0v.z, w0v.w, w1v.x, w1v.y, w1v.z, w1v.w};
                    #pragma unroll
                    for (int j = 0; j < 8; j++)
                        #pragma unroll
                        for (int p = 0; p < 8; p++)
                            acc[j][p] = fmaf(a[j], bseg[p + dx], acc[j][p]);
                }
            }
        }
        __syncthreads();
    }

    // epilogue: bias + store + BN2 partial stats (warp = 32 px-threads of one cothr)
    float* f2 = g_feat2 + (size_t)n * CH * NPX + (size_t)(y0 + r) * 64 + tcol;
    #pragma unroll
    for (int j = 0; j < 8; j++) {
        float bias = b2[co0 + j];
        #pragma unroll
        for (int p = 0; p < 8; p++) acc[j][p] += bias;
        float4 o0 = make_float4(acc[j][0], acc[j][1], acc[j][2], acc[j][3]);
        float4 o1 = make_float4(acc[j][4], acc[j][5], acc[j][6], acc[j][7]);
        *(float4*)(f2 + (size_t)(co0 + j) * NPX)     = o0;
        *(float4*)(f2 + (size_t)(co0 + j) * NPX + 4) = o1;
        float sv = 0.f, qv = 0.f;
        #pragma unroll
        for (int p = 0; p < 8; p++) { sv += acc[j][p]; qv = fmaf(acc[j][p], acc[j][p], qv); }
        #pragma unroll
        for (int off = 16; off > 0; off >>= 1) {
            sv += __shfl_down_sync(0xffffffffu, sv, off);
            qv += __shfl_down_sync(0xffffffffu, qv, off);
        }
        if (pxthr == 0) {
            g_c2part[(size_t)blockIdx.x * 128 + (co0 + j) * 2]     = sv;
            g_c2part[(size_t)blockIdx.x * 128 + (co0 + j) * 2 + 1] = qv;
        }
    }
}

// ---------------- bn2 coefficient reduce ----------------
__global__ __launch_bounds__(256) void k_bn2red(const float* __restrict__ gamma,
                                                const float* __restrict__ beta) {
    int g = blockIdx.x >> 6, c = blockIdx.x & 63;
    int tid = threadIdx.x;
    float s = 0.f, q = 0.f;
    for (int idx = tid; idx < 2048; idx += 256) {
        int nn = (idx >> 4) * 2 + g;
        int t = idx & 15;
        size_t bidx = (size_t)(nn * 16 + t) * 128;
        s += g_c2part[bidx + c * 2];
        q += g_c2part[bidx + c * 2 + 1];
    }
    __shared__ float rs[256], rq[256];
    rs[tid] = s; rq[tid] = q; __syncthreads();
    for (int st = 128; st > 0; st >>= 1) {
        if (tid < st) { rs[tid] += rs[tid + st]; rq[tid] += rq[tid + st]; }
        __syncthreads();
    }
    if (tid == 0) {
        float mean = rs[0] * (1.f / 524288.f);
        float var  = rq[0] * (1.f / 524288.f) - mean * mean;
        float a = gamma[c] * rsqrtf(var + 1e-5f);
        g_bnab[1][g][c][0] = a;
        g_bnab[1][g][c][1] = beta[c] - mean * a;
    }
}

// ---------------- bn2 + residual(+orig image broadcast) + relu ----------------
__global__ __launch_bounds__(256) void k_residual(const float* __restrict__ img) {
    size_t e = ((size_t)blockIdx.x * 256 + threadIdx.x) * 4;
    int n = (int)(e >> 18);
    int c = (int)((e >> 12) & 63);
    int p = (int)(e & 4095);
    int g = n & 1;
    float a = g_bnab[1][g][c][0], b = g_bnab[1][g][c][1];
    float4 v = *(const float4*)(g_feat2 + e);
    float4 x = *(const float4*)(img + (size_t)n * NPX + p);
    float4 o;
    o.x = fmaxf(fmaf(a, v.x, b) + x.x, 0.f);
    o.y = fmaxf(fmaf(a, v.y, b) + x.y, 0.f);
    o.z = fmaxf(fmaf(a, v.z, b) + x.z, 0.f);
    o.w = fmaxf(fmaf(a, v.w, b) + x.w, 0.f);
    *(float4*)(g_feat1 + e) = o;
}

// ---------------- fused glimpser + filterbank + glimpse contraction ----------------
// grid 512 = (b, quarter of channels). Each block recomputes Fh/Fw for its b.
__global__ __launch_bounds__(256) void k_glimpse(const float* __restrict__ gw,
                                                 const float* __restrict__ gb, int par) {
    int b = blockIdx.x >> 2, q = blockIdx.x & 3;
    int n = 2 * b + par;
    int tid = threadIdx.x;

    __shared__ float gp_s[3];
    __shared__ float ps[2][2][8];
    __shared__ float Fh_s[8][66], Fw_s[8][66];
    __shared__ float t_s[16][8][66];

    // glimpser linear: warp 0
    if (tid < 32) {
        const float* hx = g_Hx + b * HID;
        float h0 = hx[tid], h1 = hx[tid + 32], h2 = hx[tid + 64], h3 = hx[tid + 96];
        #pragma unroll
        for (int rix = 0; rix < 3; rix++) {
            const float* w = gw + rix * HID;
            float s = h0 * w[tid] + h1 * w[tid + 32] + h2 * w[tid + 64] + h3 * w[tid + 96];
            for (int off = 16; off > 0; off >>= 1) s += __shfl_down_sync(0xffffffffu, s, off);
            if (tid == 0) gp_s[rix] = tanhf(s + gb[rix]);
        }
    }
    __syncthreads();

    // Cauchy filterbanks: threads 0..127 (fs = tid>>6, i = tid&63)
    float f[8];
    int fs = tid >> 6, fi_i = tid & 63;
    if (tid < 128) {
        float d = gp_s[2];
        float delta = 8.f * (1.f - fabsf(d));
        float gamma = expf(1.f - 2.f * fabsf(d));
        float inv_g = 1.f / gamma;
        float inv_pg = 1.f / (3.14159265358979323846f * gamma);
        float center = 31.5f * (gp_s[fs] + 1.f);
        float fi = (float)fi_i;
        #pragma unroll
        for (int gg = 0; gg < 8; gg++) {
            float gpos = center + delta * ((float)gg - 3.5f);
            float u = (fi - gpos) * inv_g;
            f[gg] = inv_pg / (1.f + u * u);
        }
        int lane = tid & 31, w2i = (tid >> 5) & 1;
        #pragma unroll
        for (int gg = 0; gg < 8; gg++) {
            float s = f[gg];
            for (int off = 16; off > 0; off >>= 1) s += __shfl_down_sync(0xffffffffu, s, off);
            if (lane == 0) ps[fs][w2i][gg] = s;
        }
    }
    __syncthreads();
    if (tid < 128) {
        #pragma unroll
        for (int gg = 0; gg < 8; gg++) {
            float sum = ps[fs][0][gg] + ps[fs][1][gg];
            float v = f[gg] / (sum + 1e-4f);
            if (fs) Fw_s[gg][fi_i] = v; else Fh_s[gg][fi_i] = v;
        }
    }
    __syncthreads();

    // t[c][g][j] = sum_i Fh[g][i] * img[c][i][j]  (16 channels per block)
    int cl = tid >> 4, j0 = (tid & 15) * 4;
    int c = q * 16 + cl;
    const float* ip = g_feat1 + ((size_t)n * CH + c) * NPX;
    float acc[8][4];
    #pragma unroll
    for (int gg = 0; gg < 8; gg++)
        #pragma unroll
        for (int p = 0; p < 4; p++) acc[gg][p] = 0.f;

    #pragma unroll 4
    for (int ii = 0; ii < 64; ii++) {
        float4 v = *(const float4*)(ip + ii * 64 + j0);
        #pragma unroll
        for (int gg = 0; gg < 8; gg++) {
            float fh = Fh_s[gg][ii];
            acc[gg][0] = fmaf(fh, v.x, acc[gg][0]);
            acc[gg][1] = fmaf(fh, v.y, acc[gg][1]);
            acc[gg][2] = fmaf(fh, v.z, acc[gg][2]);
            acc[gg][3] = fmaf(fh, v.w, acc[gg][3]);
        }
    }
    #pragma unroll
    for (int gg = 0; gg < 8; gg++) {
        t_s[cl][gg][j0 + 0] = acc[gg][0];
        t_s[cl][gg][j0 + 1] = acc[gg][1];
        t_s[cl][gg][j0 + 2] = acc[gg][2];
        t_s[cl][gg][j0 + 3] = acc[gg][3];
    }
    __syncthreads();

    // gl[c][g][w] = sum_j t[c][g][j] * Fw[w][j] ; 1024 outputs, 4/thread
    #pragma unroll
    for (int k = 0; k < 4; k++) {
        int o = tid + 256 * k;
        int cc = o >> 6, gg = (o >> 3) & 7, w = o & 7;
        float s = 0.f;
        #pragma unroll 8
        for (int jj = 0; jj < 64; jj++) s = fmaf(t_s[cc][gg][jj], Fw_s[w][jj], s);
        g_flat[b * 4096 + (q * 16 + cc) * 64 + gg * 8 + w] = s;
    }
}

// ---------------- LSTM gates GEMM: gatesP[ks] = flat_chunk @ Wih_chunk^T ----------------
// grid (8 N-tiles, 16 K-splits); block tile M=128, N=64, K=256; B from g_wihT (k-major)
__global__ __launch_bounds__(256) void k_gates() {
    __shared__ __align__(16) float A_s[16][132];
    __shared__ __align__(16) float B_s[16][72];
    int tid = threadIdx.x;
    int mt = tid & 15, nt = tid >> 4;
    int r0 = blockIdx.x * 64;
    int kbase = blockIdx.y * 256;

    float acc[8][4];
    #pragma unroll
    for (int i = 0; i < 8; i++)
        #pragma unroll
        for (int j = 0; j < 4; j++) acc[i][j] = 0.f;

    for (int k0 = 0; k0 < 256; k0 += 16) {
        for (int e = tid; e < 2048; e += 256) {
            int bb = e >> 4, kk = e & 15;
            A_s[kk][bb] = g_flat[bb * 4096 + kbase + k0 + kk];
        }
        {
            int kk = tid >> 4, rr4 = (tid & 15) * 4;
            float4 v = *(const float4*)(g_wihT + (size_t)(kbase + k0 + kk) * 512 + r0 + rr4);
            *(float4*)&B_s[kk][rr4] = v;
        }
        __syncthreads();
        #pragma unroll
        for (int kk = 0; kk < 16; kk++) {
            float4 a0 = *(const float4*)&A_s[kk][mt * 8];
            float4 a1 = *(const float4*)&A_s[kk][mt * 8 + 4];
            float4 bv = *(const float4*)&B_s[kk][nt * 4];
            float a[8] = {a0.x, a0.y, a0.z, a0.w, a1.x, a1.y, a1.z, a1.w};
            float bb[4] = {bv.x, bv.y, bv.z, bv.w};
            #pragma unroll
            for (int i = 0; i < 8; i++)
                #pragma unroll
                for (int j = 0; j < 4; j++)
                    acc[i][j] = fmaf(a[i], bb[j], acc[i][j]);
        }
        __syncthreads();
    }
    #pragma unroll
    for (int i = 0; i < 8; i++)
        #pragma unroll
        for (int j = 0; j < 4; j++)
            g_gatesP[((size_t)blockIdx.y * 128 + mt * 8 + i) * 512 + r0 + nt * 4 + j] = acc[i][j];
}

// ---------------- LSTM reduce + Hx@Whh^T + pointwise update ----------------
__global__ __launch_bounds__(128) void k_update(const float* __restrict__ bih,
                                                const float* __restrict__ bhh) {
    int b = blockIdx.x, j = threadIdx.x;
    __shared__ float hx_s[128];
    hx_s[j] = g_Hx[b * 128 + j];
    __syncthreads();
    float gate[4];
    #pragma unroll
    for (int q = 0; q < 4; q++) {
        int rr = q * 128 + j;
        float s = bih[rr] + bhh[rr];
        #pragma unroll
        for (int ks = 0; ks < 16; ks++) s += g_gatesP[((size_t)ks * 128 + b) * 512 + rr];
        float s2 = 0.f;
        #pragma unroll 8
        for (int h = 0; h < 128; h++) s2 = fmaf(hx_s[h], g_whhT[h * 512 + rr], s2);
        gate[q] = s + s2;
    }
    float ig = 1.f / (1.f + expf(-gate[0]));
    float fg = 1.f / (1.f + expf(-gate[1]));
    float gg = tanhf(gate[2]);
    float og = 1.f / (1.f + expf(-gate[3]));
    float cx = fg * g_Cx[b * 128 + j] + ig * gg;
    g_Cx[b * 128 + j] = cx;
    g_Hx[b * 128 + j] = og * tanhf(cx);
}

__global__ void k_copyout(float* __restrict__ out) {
    int i = blockIdx.x * blockDim.x + threadIdx.x;
    if (i < BSZ * HID) out[i] = g_Hx[i];
}

// ---------------- launch ----------------
extern "C" void kernel_launch(void* const* d_in, const int* in_sizes, int n_in,
                              void* d_out, int out_size) {
    const float* img  = (const float*)d_in[0];
    const float* c1w  = (const float*)d_in[1];
    const float* c1b  = (const float*)d_in[2];
    const float* bn1g = (const float*)d_in[3];
    const float* bn1b = (const float*)d_in[4];
    const float* c2w  = (const float*)d_in[5];
    const float* c2b  = (const float*)d_in[6];
    const float* bn2g = (const float*)d_in[7];
    const float* bn2b = (const float*)d_in[8];
    const float* wih  = (const float*)d_in[9];
    const float* whh  = (const float*)d_in[10];
    const float* bih  = (const float*)d_in[11];
    const float* bhh  = (const float*)d_in[12];
    const float* gw   = (const float*)d_in[13];
    const float* gb   = (const float*)d_in[14];
    float* out = (float*)d_out;

    k_zero<<<32, 512>>>();
    k_prep_w2t<<<144, 256>>>(c2w);
    k_prep_wihT<<<dim3(128, 16), 256>>>(wih);
    k_prep_whhT<<<128, 512>>>(whh);

    k_conv1<<<256, 256>>>(img, c1w, c1b, 0);   // stats pass
    k_bn1red<<<128, 128>>>(bn1g, bn1b);
    k_conv1<<<256, 256>>>(img, c1w, c1b, 1);   // write relu(bn1(conv1)) -> feat3
    k_conv2<<<4096, 256>>>(c2b);               // feat3 -> feat2 (+stats partials)
    k_bn2red<<<128, 256>>>(bn2g, bn2b);
    k_residual<<<65536, 256>>>(img);

    for (int turn = 0; turn < 16; ++turn) {
        int par = (turn & 1) ? 0 : 1;   // even turn -> test (pair 1), odd -> support (pair 0)
        k_glimpse<<<512, 256>>>(gw, gb, par);
        k_gates<<<dim3(8, 16), 256>>>();
        k_update<<<128, 128>>>(bih, bhh);
    }
    k_copyout<<<32, 512>>>(out);
}